// round 12
// baseline (speedup 1.0000x reference)
#include <cuda_runtime.h>
#include <cuda_bf16.h>
#include <cstdint>

#define D      150
#define Dp     160
#define NTOT   25600     // Dp*Dp, n = j*160 + i
#define BZ     256
#define DIN    1024

// ---------------- scratch (__device__ globals; zero-init; pads never written)
__device__ __align__(16) __nv_bfloat16 g_eh[3][BZ][Dp];      // emb hi image
__device__ __align__(16) __nv_bfloat16 g_el[3][BZ][Dp];      // emb lo image
__device__ __align__(16) __nv_bfloat16 g_tbh[6][NTOT][Dp];   // T image [q][n][k] hi
__device__ __align__(16) __nv_bfloat16 g_tbl[6][NTOT][Dp];   // lo
__device__ __align__(16) __nv_bfloat16 g_wbh[6][BZ][Dp][Dp]; // w image [q][bz][j][i] hi
__device__ __align__(16) __nv_bfloat16 g_wbl[6][BZ][Dp][Dp]; // lo
__device__ __align__(16) float g_cp[4][128][128][128];       // co-parent staging

// q0 span_psh (no sym)  q1 span_pst (sym)  q2 ph_sib  q3 pt_sib
// q4 ph_cop  q5 pt_cop  (q4,q5 permuted out via g_cp + k_cop)
__constant__ int c_ZI[6] = {2,2,2,2,0,1};
__constant__ int c_XI[6] = {0,0,0,1,2,2};
__constant__ int c_YI[6] = {1,1,0,1,2,2};

// ---------------- low-level helpers ----------------------------------------
__device__ __forceinline__ uint32_t smem_u32(const void* p){
    uint32_t a;
    asm("{ .reg .u64 t; cvta.to.shared.u64 t, %1; cvt.u32.u64 %0, t; }" : "=r"(a) : "l"(p));
    return a;
}
__device__ __forceinline__ void split_pack(float a, float b, uint32_t& h, uint32_t& l){
    __nv_bfloat16 ah = __float2bfloat16(a), bh = __float2bfloat16(b);
    __nv_bfloat16 al = __float2bfloat16(a - __bfloat162float(ah));
    __nv_bfloat16 bl = __float2bfloat16(b - __bfloat162float(bh));
    h = (uint32_t)__bfloat16_as_ushort(ah) | ((uint32_t)__bfloat16_as_ushort(bh) << 16);
    l = (uint32_t)__bfloat16_as_ushort(al) | ((uint32_t)__bfloat16_as_ushort(bl) << 16);
}
__device__ __forceinline__ void mma16816(float* c, const uint32_t* a, uint32_t b0, uint32_t b1){
    asm volatile("mma.sync.aligned.m16n8k16.row.col.f32.bf16.bf16.f32 "
        "{%0,%1,%2,%3}, {%4,%5,%6,%7}, {%8,%9}, {%0,%1,%2,%3};"
        : "+f"(c[0]), "+f"(c[1]), "+f"(c[2]), "+f"(c[3])
        : "r"(a[0]), "r"(a[1]), "r"(a[2]), "r"(a[3]), "r"(b0), "r"(b1));
}
__device__ __forceinline__ void ldsm4(uint32_t* r, uint32_t a){
    asm volatile("ldmatrix.sync.aligned.m8n8.x4.shared.b16 {%0,%1,%2,%3}, [%4];"
        : "=r"(r[0]), "=r"(r[1]), "=r"(r[2]), "=r"(r[3]) : "r"(a));
}
__device__ __forceinline__ void cpa16(uint32_t s, const void* g){
    asm volatile("cp.async.cg.shared.global [%0], [%1], 16;" :: "r"(s), "l"(g));
}
#define CP_COMMIT() asm volatile("cp.async.commit_group;" ::: "memory")
#define CP_WAIT1()  asm volatile("cp.async.wait_group 1;" ::: "memory")
#define CP_WAIT0()  asm volatile("cp.async.wait_group 0;" ::: "memory")

// 32B-row layout (k16 chunks): 2x16B units/row, XOR swizzle (R7-proven)
__device__ __forceinline__ uint32_t swz(int row, int u){
    return (uint32_t)(row * 32 + (((u ^ (row >> 2)) & 1) << 4));
}
__device__ __forceinline__ uint32_t lds_addr(uint32_t base, int r0, int ln){
    int g = ln >> 3;
    int row = r0 + ((g & 1) << 3) + (ln & 7);
    return base + swz(row, g >> 1);
}
// 64B-row layout (k32 chunks), R9-proven
__device__ __forceinline__ uint32_t swz64(int row, int u){
    return (uint32_t)(row * 64 + 16 * ((u ^ (row >> 1)) & 3));
}
__device__ __forceinline__ uint32_t a64(uint32_t base, int r0, int ln, int c){
    int g = ln >> 3;
    int row = r0 + ((g & 1) << 3) + (ln & 7);
    return base + swz64(row, 2 * c + (g >> 1));
}
// 320B-row image layout (v), R7-proven
__device__ __forceinline__ uint32_t voff(int row, int j){
    return (uint32_t)(row * 320 + 16 * ((j >> 3) ^ ((row >> 1) & 3)) + (j & 7) * 2);
}
__device__ __forceinline__ uint32_t vuoff(int row, int u){
    return (uint32_t)(row * 320 + 16 * (u ^ ((row >> 1) & 3)));
}
__device__ __forceinline__ uint32_t ldsV(uint32_t base, int r0, int ln, int u0){
    int g = ln >> 3;
    int row = r0 + ((g & 1) << 3) + (ln & 7);
    return base + vuoff(row, u0 + (g >> 1));
}
// ILP-4 split-major 12-MMA block
#define MMA_BLK(t00, t01, t10, t11, ah, al, bh, bl) do { \
    mma16816(t00, ah[0], bh[0], bh[2]); \
    mma16816(t01, ah[0], bh[1], bh[3]); \
    mma16816(t10, ah[1], bh[0], bh[2]); \
    mma16816(t11, ah[1], bh[1], bh[3]); \
    mma16816(t00, ah[0], bl[0], bl[2]); \
    mma16816(t01, ah[0], bl[1], bl[3]); \
    mma16816(t10, ah[1], bl[0], bl[2]); \
    mma16816(t11, ah[1], bl[1], bl[3]); \
    mma16816(t00, al[0], bh[0], bh[2]); \
    mma16816(t01, al[0], bh[1], bh[3]); \
    mma16816(t10, al[1], bh[0], bh[2]); \
    mma16816(t11, al[1], bh[1], bh[3]); \
} while(0)

// ---------------- MLP (row-blocked; W streamed once per 8-row block) --------
// grid (3 e, 32 row-tiles), 160 threads; writes split-bf16 images directly.
// Per-thread k-order identical to prior version -> bit-identical outputs.
__global__ void k_mlp(const float* __restrict__ x,
                      const float* __restrict__ W0, const float* __restrict__ b0,
                      const float* __restrict__ W1, const float* __restrict__ b1,
                      const float* __restrict__ W2, const float* __restrict__ b2)
{
    int e = blockIdx.x, r0 = blockIdx.y * 8;
    const float* W  = (e == 0) ? W0 : (e == 1) ? W1 : W2;
    const float* bb = (e == 0) ? b0 : (e == 1) ? b1 : b2;
    __shared__ float xs[8][DIN];
    int tid = threadIdx.x;     // 0..159
    for (int i = tid; i < 8 * DIN; i += 160) {
        int r = i >> 10, k = i & 1023;
        xs[r][k] = x[(r0 + r) * DIN + k];
    }
    __syncthreads();
    if (tid < D) {
        float acc[8];
        #pragma unroll
        for (int r = 0; r < 8; ++r) acc[r] = bb[tid];
        for (int k = 0; k < DIN; ++k) {
            float wv = W[k * D + tid];
            #pragma unroll
            for (int r = 0; r < 8; ++r) acc[r] += xs[r][k] * wv;
        }
        #pragma unroll
        for (int r = 0; r < 8; ++r) {
            float v = (acc[r] >= 0.f) ? acc[r] : 0.1f * acc[r];
            __nv_bfloat16 vh = __float2bfloat16(v);
            __nv_bfloat16 vl = __float2bfloat16(v - __bfloat162float(vh));
            g_eh[e][r0 + r][tid] = vh;
            g_el[e][r0 + r][tid] = vl;
        }
    }
}

// ---------------- T[i][k][j] -> TB[q][(j*160+i)][k] hi/lo -------------------
__global__ void k_timg(const float* __restrict__ T0, const float* __restrict__ T1,
                       const float* __restrict__ T2, const float* __restrict__ T3,
                       const float* __restrict__ T4, const float* __restrict__ T5)
{
    int q = blockIdx.z, i = blockIdx.y, j0 = blockIdx.x * 32;
    const float* T = (q==0)?T0:(q==1)?T1:(q==2)?T2:(q==3)?T3:(q==4)?T4:T5;
    __shared__ float ts[32][152];
    int tid = threadIdx.x;
    for (int t = tid; t < 150 * 32; t += 256) {
        int k = t >> 5, j = t & 31;
        if (j0 + j < D) ts[j][k] = T[(i * D + k) * D + j0 + j];
    }
    __syncthreads();
    for (int t = tid; t < 32 * 75; t += 256) {
        int j = t / 75, kp = t % 75;
        if (j0 + j < D) {
            uint32_t h, l;
            split_pack(ts[j][2*kp], ts[j][2*kp+1], h, l);
            int n = (j0 + j) * Dp + i;
            *(uint32_t*)&g_tbh[q][n][2*kp] = h;
            *(uint32_t*)&g_tbl[q][n][2*kp] = l;
        }
    }
}

// ---------------- stage A: w = Z . TB^T, k32 chunks (R9 exact) --------------
__global__ void __launch_bounds__(256, 2) k_stageA()
{
    extern __shared__ __align__(16) unsigned char smA[];   // 3 x 32768
    uint32_t sb = smem_u32(smA);
    int q = blockIdx.z, m0 = blockIdx.y * 128, n0 = blockIdx.x * 128;
    int tid = threadIdx.x, w = tid >> 5, ln = tid & 31;
    int wm = w & 3, wn = w >> 2;
    int zi = c_ZI[q];

    int pr = tid >> 2, pu = tid & 3;
    uint32_t sw0 = swz64(pr, pu);
    const __nv_bfloat16* gpA[4];
    gpA[0] = &g_eh[zi][0][0]  + (size_t)(m0 + pr) * Dp + pu * 8;
    gpA[1] = &g_el[zi][0][0]  + (size_t)(m0 + pr) * Dp + pu * 8;
    gpA[2] = &g_tbh[q][0][0]  + (size_t)(n0 + pr) * Dp + pu * 8;
    gpA[3] = &g_tbl[q][0][0]  + (size_t)(n0 + pr) * Dp + pu * 8;

    float acc[2][8][4];
    #pragma unroll
    for (int a = 0; a < 2; ++a)
        #pragma unroll
        for (int b = 0; b < 8; ++b)
            #pragma unroll
            for (int c = 0; c < 4; ++c) acc[a][b][c] = 0.f;

    #define PREF_A(slot, kc) do { \
        if ((kc) < Dp) { \
            uint32_t db = sb + (slot) * 32768 + sw0; \
            _Pragma("unroll") \
            for (int a = 0; a < 4; ++a) { \
                cpa16(db + a * 8192,        gpA[a] + (kc)); \
                cpa16(db + a * 8192 + 4096, gpA[a] + 64 * Dp + (kc)); \
            } \
        } \
        CP_COMMIT(); \
    } while(0)

    PREF_A(0, 0);
    PREF_A(1, 32);
    for (int ks = 0; ks < 5; ++ks) {
        CP_WAIT1();
        __syncthreads();
        PREF_A((ks + 2) % 3, (ks + 2) * 32);
        uint32_t base = sb + (ks % 3) * 32768;
        #pragma unroll
        for (int c = 0; c < 2; ++c) {
            uint32_t ah[2][4], al[2][4];
            #pragma unroll
            for (int mt = 0; mt < 2; ++mt) {
                ldsm4(ah[mt], a64(base,        wm * 32 + mt * 16, ln, c));
                ldsm4(al[mt], a64(base + 8192, wm * 32 + mt * 16, ln, c));
            }
            #pragma unroll
            for (int p = 0; p < 4; ++p) {
                uint32_t bh[4], bl[4];
                ldsm4(bh, a64(base + 16384, wn * 64 + p * 16, ln, c));
                ldsm4(bl, a64(base + 24576, wn * 64 + p * 16, ln, c));
                MMA_BLK(acc[0][2*p], acc[0][2*p+1], acc[1][2*p], acc[1][2*p+1], ah, al, bh, bl);
            }
        }
    }
    #undef PREF_A

    __nv_bfloat16* WH = &g_wbh[0][0][0][0];
    __nv_bfloat16* WL = &g_wbl[0][0][0][0];
    int yb = 2 * (ln & 3);
    #pragma unroll
    for (int mt = 0; mt < 2; ++mt) {
        int mA = m0 + wm * 32 + mt * 16 + (ln >> 2);
        #pragma unroll
        for (int nt = 0; nt < 8; ++nt) {
            int n = n0 + wn * 64 + nt * 8 + yb;
            size_t off0 = ((size_t)(q * BZ + mA)) * 25600 + n;
            size_t off1 = off0 + (size_t)8 * 25600;
            uint32_t h, l;
            split_pack(acc[mt][nt][0], acc[mt][nt][1], h, l);
            *(uint32_t*)(WH + off0) = h; *(uint32_t*)(WL + off0) = l;
            split_pack(acc[mt][nt][2], acc[mt][nt][3], h, l);
            *(uint32_t*)(WH + off1) = h; *(uint32_t*)(WL + off1) = l;
        }
    }
}

// ---------------- fused B+C per (q,bz): 256 thr, 2 CTA/SM -------------------
__device__ __forceinline__ void prefB(uint32_t sb, int slot, int k0, int tid,
    const __nv_bfloat16* Xh, const __nv_bfloat16* Xl,
    const __nv_bfloat16* Wh, const __nv_bfloat16* Wl)
{
    if (k0 < Dp) {
        for (int t = tid; t < 1152; t += 256) {
            uint32_t dst; const __nv_bfloat16* g;
            if (t < 512) {
                int img = t >> 8, rr = (t >> 1) & 127, u = t & 1;
                dst = sb + slot * 18432 + img * 4096 + swz(rr, u);
                g = (img ? Xl : Xh) + (size_t)rr * Dp + k0 + u * 8;
            } else {
                int t2 = t - 512;
                int img = t2 / 320, r2 = t2 - img * 320;
                int rr = r2 >> 1, u = r2 & 1;
                dst = sb + slot * 18432 + 8192 + img * 5120 + swz(rr, u);
                g = (img ? Wl : Wh) + (size_t)rr * Dp + k0 + u * 8;
            }
            cpa16(dst, g);
        }
    }
    CP_COMMIT();
}

__global__ void __launch_bounds__(256, 2) k_fusedBC(float* __restrict__ out)
{
    extern __shared__ __align__(16) unsigned char dynsm[];
    uint32_t sb = smem_u32(dynsm);
    int q = blockIdx.y, bz = blockIdx.x, b = bz >> 7, z = bz & 127;
    int tid = threadIdx.x, w = tid >> 5, ln = tid & 31;
    int wm = w & 3, wn = w >> 2;                    // stage B mapping (4x2)
    int tm = (w < 4) ? w : 7 - w, tn = w >> 2;      // stage C mapping (balanced)
    int pb0 = (q == 0) ? 0 : max(0, min(4, 2 * tm - 4 * tn));

    const __nv_bfloat16 *Xh = &g_eh[c_XI[q]][b*128][0], *Xl = &g_el[c_XI[q]][b*128][0];
    const __nv_bfloat16 *Wh = &g_wbh[q][bz][0][0],      *Wl = &g_wbl[q][bz][0][0];
    const __nv_bfloat16 *Yh = &g_eh[c_YI[q]][b*128][0], *Yl = &g_el[c_YI[q]][b*128][0];

    // ---- stage B (warp tile 32x80, k16, 3-slot, 1 sync/iter)
    float accB[2][10][4];
    #pragma unroll
    for (int mt = 0; mt < 2; ++mt)
        #pragma unroll
        for (int i = 0; i < 10; ++i)
            #pragma unroll
            for (int c = 0; c < 4; ++c) accB[mt][i][c] = 0.f;

    prefB(sb, 0, 0,  tid, Xh, Xl, Wh, Wl);
    prefB(sb, 1, 16, tid, Xh, Xl, Wh, Wl);
    for (int ks = 0; ks < 10; ++ks) {
        CP_WAIT1();
        __syncthreads();
        prefB(sb, (ks + 2) % 3, (ks + 2) * 16, tid, Xh, Xl, Wh, Wl);
        uint32_t base = sb + (ks % 3) * 18432;
        uint32_t ah[2][4], al[2][4];
        #pragma unroll
        for (int mt = 0; mt < 2; ++mt) {
            ldsm4(ah[mt], lds_addr(base,        wm * 32 + mt * 16, ln));
            ldsm4(al[mt], lds_addr(base + 4096, wm * 32 + mt * 16, ln));
        }
        #pragma unroll
        for (int p = 0; p < 5; ++p) {
            uint32_t bh[4], bl[4];
            ldsm4(bh, lds_addr(base + 8192,  wn * 80 + p * 16, ln));
            ldsm4(bl, lds_addr(base + 13312, wn * 80 + p * 16, ln));
            MMA_BLK(accB[0][2*p], accB[0][2*p+1], accB[1][2*p], accB[1][2*p+1], ah, al, bh, bl);
        }
    }
    CP_WAIT0();
    __syncthreads();   // stage-B smem reads done; region reused for v images

    // ---- Y chunk prefetch macro (k16 chunks, 3 slots at [81920,106496))
    #define PREF_Y(slot, kc) do { \
        if ((kc) < Dp) { \
            int t = tid; \
            _Pragma("unroll") \
            for (int it = 0; it < 2; ++it, t += 256) { \
                int img = t >> 8, r2 = t & 255; \
                int row = r2 >> 1, u = r2 & 1; \
                cpa16(sb + 81920 + (slot) * 8192 + img * 4096 + swz(row, u), \
                      (img ? Yl : Yh) + (size_t)row * Dp + (kc) + u * 8); \
            } \
        } \
        CP_COMMIT(); \
    } while(0)

    PREF_Y(0, 0);
    PREF_Y(1, 16);

    // ---- v -> split-bf16 smem images at [0,81920)  (hi@0, lo@40960)
    #pragma unroll
    for (int mt = 0; mt < 2; ++mt) {
        #pragma unroll
        for (int n8 = 0; n8 < 10; ++n8) {
            int j  = wn * 80 + n8 * 8 + 2 * (ln & 3);
            int x1 = wm * 32 + mt * 16 + (ln >> 2);
            uint32_t h, l;
            split_pack(accB[mt][n8][0], accB[mt][n8][1], h, l);
            *(uint32_t*)(dynsm + voff(x1, j))         = h;
            *(uint32_t*)(dynsm + 40960 + voff(x1, j)) = l;
            split_pack(accB[mt][n8][2], accB[mt][n8][3], h, l);
            *(uint32_t*)(dynsm + voff(x1 + 8, j))         = h;
            *(uint32_t*)(dynsm + 40960 + voff(x1 + 8, j)) = l;
        }
    }

    // ---- stage C (warp tile 32x64, A from v-images, B from streamed Y)
    float accC[2][8][4];
    #pragma unroll
    for (int mt = 0; mt < 2; ++mt)
        #pragma unroll
        for (int i = 0; i < 8; ++i)
            #pragma unroll
            for (int c = 0; c < 4; ++c) accC[mt][i][c] = 0.f;

    for (int kk = 0; kk < 10; ++kk) {
        CP_WAIT1();
        __syncthreads();          // (first iter also publishes v images)
        PREF_Y((kk + 2) % 3, (kk + 2) * 16);
        uint32_t ybase = sb + 81920 + (kk % 3) * 8192;
        int u0 = kk * 2;
        uint32_t ah[2][4], al[2][4];
        if (pb0 < 4) {            // skip A-frag loads for zero-work warps
            #pragma unroll
            for (int mt = 0; mt < 2; ++mt) {
                ldsm4(ah[mt], ldsV(sb,         tm * 32 + mt * 16, ln, u0));
                ldsm4(al[mt], ldsV(sb + 40960, tm * 32 + mt * 16, ln, u0));
            }
        }
        #pragma unroll
        for (int pb = 0; pb < 4; ++pb) {
            if (pb >= pb0) {
                uint32_t bh[4], bl[4];
                ldsm4(bh, lds_addr(ybase,        tn * 64 + pb * 16, ln));
                ldsm4(bl, lds_addr(ybase + 4096, tn * 64 + pb * 16, ln));
                MMA_BLK(accC[0][2*pb], accC[0][2*pb+1], accC[1][2*pb], accC[1][2*pb+1],
                        ah, al, bh, bl);
            }
        }
    }
    #undef PREF_Y
    CP_WAIT0();
    __syncthreads();   // stage-C smem reads done; reuse region for s-tile

    // ---- epilogue: stage s tile, triu_sym on read, coalesced out
    float* ss = (float*)dynsm;   // [128][130]
    #pragma unroll
    for (int mt = 0; mt < 2; ++mt) {
        int x = tm * 32 + mt * 16 + (ln >> 2);
        #pragma unroll
        for (int nt = 0; nt < 8; ++nt) {
            int y = tn * 64 + nt * 8 + 2 * (ln & 3);
            ss[x * 130 + y]           = accC[mt][nt][0];
            ss[x * 130 + y + 1]       = accC[mt][nt][1];
            ss[(x + 8) * 130 + y]     = accC[mt][nt][2];
            ss[(x + 8) * 130 + y + 1] = accC[mt][nt][3];
        }
    }
    __syncthreads();

    bool dosym = (q != 0);
    float* o;
    if (q < 4) o = out + (size_t)q * 4194304 + (size_t)bz * 16384;
    else       o = &g_cp[(q - 4) * 2 + b][z][0][0];
    int c0 = ln * 4;
    #pragma unroll
    for (int rr = 0; rr < 16; ++rr) {
        int r = w * 16 + rr;
        const float* pr2 = ss + r * 130;
        float4 v;
        v.x = (!dosym || r <= c0    ) ? pr2[c0]     : ss[(c0)     * 130 + r];
        v.y = (!dosym || r <= c0 + 1) ? pr2[c0 + 1] : ss[(c0 + 1) * 130 + r];
        v.z = (!dosym || r <= c0 + 2) ? pr2[c0 + 2] : ss[(c0 + 2) * 130 + r];
        v.w = (!dosym || r <= c0 + 3) ? pr2[c0 + 3] : ss[(c0 + 3) * 130 + r];
        *(float4*)(o + (size_t)r * 128 + c0) = v;
    }
}

// ---------------- co-parent permute: g_cp[t*2+b][z][x][y] -> out[b][x][y][z]
__global__ void k_cop(float* __restrict__ out)
{
    __shared__ float ts[32][33];
    int tile = blockIdx.x;
    int x    = blockIdx.y;
    int tb   = blockIdx.z;
    int z0 = (tile >> 2) * 32, y0 = (tile & 3) * 32;
    int tx = threadIdx.x, ty = threadIdx.y;
    const float* src = &g_cp[tb][0][x][0];
    #pragma unroll
    for (int i = ty; i < 32; i += 8)
        ts[i][tx] = src[(size_t)(z0 + i) * 16384 + y0 + tx];
    __syncthreads();
    float* dst = out + (size_t)(4 + (tb >> 1)) * 4194304 + (size_t)(tb & 1) * 2097152
               + (size_t)x * 16384;
    #pragma unroll
    for (int i = ty; i < 32; i += 8)
        dst[(size_t)(y0 + i) * 128 + z0 + tx] = ts[tx][i];
}

// ---------------------------------------------------------------------------
extern "C" void kernel_launch(void* const* d_in, const int* in_sizes, int n_in,
                              void* d_out, int out_size)
{
    const float* x      = (const float*)d_in[0];
    const float* W_sh   = (const float*)d_in[1];
    const float* b_sh   = (const float*)d_in[2];
    const float* W_st   = (const float*)d_in[3];
    const float* b_st   = (const float*)d_in[4];
    const float* W_p    = (const float*)d_in[5];
    const float* b_p    = (const float*)d_in[6];
    const float* T_pt   = (const float*)d_in[7];
    const float* T_ph   = (const float*)d_in[8];
    const float* T_phsib= (const float*)d_in[9];
    const float* T_ptsib= (const float*)d_in[10];
    const float* T_phcop= (const float*)d_in[11];
    const float* T_ptcop= (const float*)d_in[12];

    static bool attr_done = false;
    if (!attr_done) {
        cudaFuncSetAttribute(k_stageA,  cudaFuncAttributeMaxDynamicSharedMemorySize, 98304);
        cudaFuncSetAttribute(k_fusedBC, cudaFuncAttributeMaxDynamicSharedMemorySize, 106496);
        attr_done = true;
    }

    k_mlp   <<<dim3(3, 32), 160>>>(x, W_sh, b_sh, W_st, b_st, W_p, b_p);
    // q order: 0=T_ph 1=T_pt 2=T_phsib 3=T_ptsib 4=T_phcop 5=T_ptcop
    k_timg  <<<dim3(5, D, 6), 256>>>(T_ph, T_pt, T_phsib, T_ptsib, T_phcop, T_ptcop);
    k_stageA<<<dim3(200, 2, 6), 256, 98304>>>();
    k_fusedBC<<<dim3(BZ, 6), 256, 106496>>>((float*)d_out);
    k_cop   <<<dim3(16, 128, 4), dim3(32, 8)>>>((float*)d_out);
}

// round 13
// speedup vs baseline: 1.1779x; 1.1779x over previous
#include <cuda_runtime.h>
#include <cuda_bf16.h>
#include <cstdint>

#define D      150
#define Dp     160
#define NTOT   25600     // Dp*Dp, n = j*160 + i
#define BZ     256
#define DIN    1024

// ---------------- scratch (__device__ globals; zero-init; pads never written)
__device__ __align__(16) __nv_bfloat16 g_eh[3][BZ][Dp];      // emb hi image
__device__ __align__(16) __nv_bfloat16 g_el[3][BZ][Dp];      // emb lo image
__device__ __align__(16) __nv_bfloat16 g_tbh[6][NTOT][Dp];   // T image [q][n][k] hi
__device__ __align__(16) __nv_bfloat16 g_tbl[6][NTOT][Dp];   // lo
__device__ __align__(16) __nv_bfloat16 g_wbh[6][BZ][Dp][Dp]; // w image [q][bz][j][i] hi
__device__ __align__(16) __nv_bfloat16 g_wbl[6][BZ][Dp][Dp]; // lo
__device__ __align__(16) float g_cp[4][128][128][128];       // co-parent staging

// q0 span_psh (no sym)  q1 span_pst (sym)  q2 ph_sib  q3 pt_sib
// q4 ph_cop  q5 pt_cop  (q4,q5 permuted out via g_cp + k_cop)
__constant__ int c_ZI[6] = {2,2,2,2,0,1};
__constant__ int c_XI[6] = {0,0,0,1,2,2};
__constant__ int c_YI[6] = {1,1,0,1,2,2};

// ---------------- low-level helpers ----------------------------------------
__device__ __forceinline__ uint32_t smem_u32(const void* p){
    uint32_t a;
    asm("{ .reg .u64 t; cvta.to.shared.u64 t, %1; cvt.u32.u64 %0, t; }" : "=r"(a) : "l"(p));
    return a;
}
__device__ __forceinline__ void split_pack(float a, float b, uint32_t& h, uint32_t& l){
    __nv_bfloat16 ah = __float2bfloat16(a), bh = __float2bfloat16(b);
    __nv_bfloat16 al = __float2bfloat16(a - __bfloat162float(ah));
    __nv_bfloat16 bl = __float2bfloat16(b - __bfloat162float(bh));
    h = (uint32_t)__bfloat16_as_ushort(ah) | ((uint32_t)__bfloat16_as_ushort(bh) << 16);
    l = (uint32_t)__bfloat16_as_ushort(al) | ((uint32_t)__bfloat16_as_ushort(bl) << 16);
}
__device__ __forceinline__ void mma16816(float* c, const uint32_t* a, uint32_t b0, uint32_t b1){
    asm volatile("mma.sync.aligned.m16n8k16.row.col.f32.bf16.bf16.f32 "
        "{%0,%1,%2,%3}, {%4,%5,%6,%7}, {%8,%9}, {%0,%1,%2,%3};"
        : "+f"(c[0]), "+f"(c[1]), "+f"(c[2]), "+f"(c[3])
        : "r"(a[0]), "r"(a[1]), "r"(a[2]), "r"(a[3]), "r"(b0), "r"(b1));
}
__device__ __forceinline__ void ldsm4(uint32_t* r, uint32_t a){
    asm volatile("ldmatrix.sync.aligned.m8n8.x4.shared.b16 {%0,%1,%2,%3}, [%4];"
        : "=r"(r[0]), "=r"(r[1]), "=r"(r[2]), "=r"(r[3]) : "r"(a));
}
__device__ __forceinline__ void cpa16(uint32_t s, const void* g){
    asm volatile("cp.async.cg.shared.global [%0], [%1], 16;" :: "r"(s), "l"(g));
}
#define CP_COMMIT() asm volatile("cp.async.commit_group;" ::: "memory")
#define CP_WAIT1()  asm volatile("cp.async.wait_group 1;" ::: "memory")
#define CP_WAIT0()  asm volatile("cp.async.wait_group 0;" ::: "memory")

// 32B-row layout (k16 chunks): 2x16B units/row, XOR swizzle (R7-proven)
__device__ __forceinline__ uint32_t swz(int row, int u){
    return (uint32_t)(row * 32 + (((u ^ (row >> 2)) & 1) << 4));
}
__device__ __forceinline__ uint32_t lds_addr(uint32_t base, int r0, int ln){
    int g = ln >> 3;
    int row = r0 + ((g & 1) << 3) + (ln & 7);
    return base + swz(row, g >> 1);
}
// 64B-row layout (k32 chunks), R9-proven
__device__ __forceinline__ uint32_t swz64(int row, int u){
    return (uint32_t)(row * 64 + 16 * ((u ^ (row >> 1)) & 3));
}
__device__ __forceinline__ uint32_t a64(uint32_t base, int r0, int ln, int c){
    int g = ln >> 3;
    int row = r0 + ((g & 1) << 3) + (ln & 7);
    return base + swz64(row, 2 * c + (g >> 1));
}
// 320B-row image layout (v), R7-proven
__device__ __forceinline__ uint32_t voff(int row, int j){
    return (uint32_t)(row * 320 + 16 * ((j >> 3) ^ ((row >> 1) & 3)) + (j & 7) * 2);
}
__device__ __forceinline__ uint32_t vuoff(int row, int u){
    return (uint32_t)(row * 320 + 16 * (u ^ ((row >> 1) & 3)));
}
__device__ __forceinline__ uint32_t ldsV(uint32_t base, int r0, int ln, int u0){
    int g = ln >> 3;
    int row = r0 + ((g & 1) << 3) + (ln & 7);
    return base + vuoff(row, u0 + (g >> 1));
}
// ILP-4 split-major 12-MMA block
#define MMA_BLK(t00, t01, t10, t11, ah, al, bh, bl) do { \
    mma16816(t00, ah[0], bh[0], bh[2]); \
    mma16816(t01, ah[0], bh[1], bh[3]); \
    mma16816(t10, ah[1], bh[0], bh[2]); \
    mma16816(t11, ah[1], bh[1], bh[3]); \
    mma16816(t00, ah[0], bl[0], bl[2]); \
    mma16816(t01, ah[0], bl[1], bl[3]); \
    mma16816(t10, ah[1], bl[0], bl[2]); \
    mma16816(t11, ah[1], bl[1], bl[3]); \
    mma16816(t00, al[0], bh[0], bh[2]); \
    mma16816(t01, al[0], bh[1], bh[3]); \
    mma16816(t10, al[1], bh[0], bh[2]); \
    mma16816(t11, al[1], bh[1], bh[3]); \
} while(0)

// ---------------- MLP (4-row blocked; merged split-bf16 image write) --------
// grid (3 e, 64 row-tiles), 160 threads. W traffic 471 -> 118 MB; 192 blocks
// keep latency hidden. Per-(row,c) k-order identical -> bit-identical emb.
__global__ void k_mlp(const float* __restrict__ x,
                      const float* __restrict__ W0, const float* __restrict__ b0,
                      const float* __restrict__ W1, const float* __restrict__ b1,
                      const float* __restrict__ W2, const float* __restrict__ b2)
{
    int e = blockIdx.x, r0 = blockIdx.y * 4;
    const float* W  = (e == 0) ? W0 : (e == 1) ? W1 : W2;
    const float* bb = (e == 0) ? b0 : (e == 1) ? b1 : b2;
    __shared__ float xs[4][DIN];
    int tid = threadIdx.x;     // 0..159
    for (int i = tid; i < 4 * DIN; i += 160) {
        int r = i >> 10, k = i & 1023;
        xs[r][k] = x[(r0 + r) * DIN + k];
    }
    __syncthreads();
    if (tid < D) {
        float acc[4];
        #pragma unroll
        for (int r = 0; r < 4; ++r) acc[r] = bb[tid];
        #pragma unroll 8
        for (int k = 0; k < DIN; ++k) {
            float wv = W[k * D + tid];
            #pragma unroll
            for (int r = 0; r < 4; ++r) acc[r] += xs[r][k] * wv;
        }
        #pragma unroll
        for (int r = 0; r < 4; ++r) {
            float v = (acc[r] >= 0.f) ? acc[r] : 0.1f * acc[r];
            __nv_bfloat16 vh = __float2bfloat16(v);
            __nv_bfloat16 vl = __float2bfloat16(v - __bfloat162float(vh));
            g_eh[e][r0 + r][tid] = vh;
            g_el[e][r0 + r][tid] = vl;
        }
    }
}

// ---------------- T[i][k][j] -> TB[q][(j*160+i)][k] hi/lo -------------------
__global__ void k_timg(const float* __restrict__ T0, const float* __restrict__ T1,
                       const float* __restrict__ T2, const float* __restrict__ T3,
                       const float* __restrict__ T4, const float* __restrict__ T5)
{
    int q = blockIdx.z, i = blockIdx.y, j0 = blockIdx.x * 32;
    const float* T = (q==0)?T0:(q==1)?T1:(q==2)?T2:(q==3)?T3:(q==4)?T4:T5;
    __shared__ float ts[32][152];
    int tid = threadIdx.x;
    for (int t = tid; t < 150 * 32; t += 256) {
        int k = t >> 5, j = t & 31;
        if (j0 + j < D) ts[j][k] = T[(i * D + k) * D + j0 + j];
    }
    __syncthreads();
    for (int t = tid; t < 32 * 75; t += 256) {
        int j = t / 75, kp = t % 75;
        if (j0 + j < D) {
            uint32_t h, l;
            split_pack(ts[j][2*kp], ts[j][2*kp+1], h, l);
            int n = (j0 + j) * Dp + i;
            *(uint32_t*)&g_tbh[q][n][2*kp] = h;
            *(uint32_t*)&g_tbl[q][n][2*kp] = l;
        }
    }
}

// ---------------- stage A: w = Z . TB^T, k32 chunks (R9 exact) --------------
__global__ void __launch_bounds__(256, 2) k_stageA()
{
    extern __shared__ __align__(16) unsigned char smA[];   // 3 x 32768
    uint32_t sb = smem_u32(smA);
    int q = blockIdx.z, m0 = blockIdx.y * 128, n0 = blockIdx.x * 128;
    int tid = threadIdx.x, w = tid >> 5, ln = tid & 31;
    int wm = w & 3, wn = w >> 2;
    int zi = c_ZI[q];

    int pr = tid >> 2, pu = tid & 3;
    uint32_t sw0 = swz64(pr, pu);
    const __nv_bfloat16* gpA[4];
    gpA[0] = &g_eh[zi][0][0]  + (size_t)(m0 + pr) * Dp + pu * 8;
    gpA[1] = &g_el[zi][0][0]  + (size_t)(m0 + pr) * Dp + pu * 8;
    gpA[2] = &g_tbh[q][0][0]  + (size_t)(n0 + pr) * Dp + pu * 8;
    gpA[3] = &g_tbl[q][0][0]  + (size_t)(n0 + pr) * Dp + pu * 8;

    float acc[2][8][4];
    #pragma unroll
    for (int a = 0; a < 2; ++a)
        #pragma unroll
        for (int b = 0; b < 8; ++b)
            #pragma unroll
            for (int c = 0; c < 4; ++c) acc[a][b][c] = 0.f;

    #define PREF_A(slot, kc) do { \
        if ((kc) < Dp) { \
            uint32_t db = sb + (slot) * 32768 + sw0; \
            _Pragma("unroll") \
            for (int a = 0; a < 4; ++a) { \
                cpa16(db + a * 8192,        gpA[a] + (kc)); \
                cpa16(db + a * 8192 + 4096, gpA[a] + 64 * Dp + (kc)); \
            } \
        } \
        CP_COMMIT(); \
    } while(0)

    PREF_A(0, 0);
    PREF_A(1, 32);
    for (int ks = 0; ks < 5; ++ks) {
        CP_WAIT1();
        __syncthreads();
        PREF_A((ks + 2) % 3, (ks + 2) * 32);
        uint32_t base = sb + (ks % 3) * 32768;
        #pragma unroll
        for (int c = 0; c < 2; ++c) {
            uint32_t ah[2][4], al[2][4];
            #pragma unroll
            for (int mt = 0; mt < 2; ++mt) {
                ldsm4(ah[mt], a64(base,        wm * 32 + mt * 16, ln, c));
                ldsm4(al[mt], a64(base + 8192, wm * 32 + mt * 16, ln, c));
            }
            #pragma unroll
            for (int p = 0; p < 4; ++p) {
                uint32_t bh[4], bl[4];
                ldsm4(bh, a64(base + 16384, wn * 64 + p * 16, ln, c));
                ldsm4(bl, a64(base + 24576, wn * 64 + p * 16, ln, c));
                MMA_BLK(acc[0][2*p], acc[0][2*p+1], acc[1][2*p], acc[1][2*p+1], ah, al, bh, bl);
            }
        }
    }
    #undef PREF_A

    __nv_bfloat16* WH = &g_wbh[0][0][0][0];
    __nv_bfloat16* WL = &g_wbl[0][0][0][0];
    int yb = 2 * (ln & 3);
    #pragma unroll
    for (int mt = 0; mt < 2; ++mt) {
        int mA = m0 + wm * 32 + mt * 16 + (ln >> 2);
        #pragma unroll
        for (int nt = 0; nt < 8; ++nt) {
            int n = n0 + wn * 64 + nt * 8 + yb;
            size_t off0 = ((size_t)(q * BZ + mA)) * 25600 + n;
            size_t off1 = off0 + (size_t)8 * 25600;
            uint32_t h, l;
            split_pack(acc[mt][nt][0], acc[mt][nt][1], h, l);
            *(uint32_t*)(WH + off0) = h; *(uint32_t*)(WL + off0) = l;
            split_pack(acc[mt][nt][2], acc[mt][nt][3], h, l);
            *(uint32_t*)(WH + off1) = h; *(uint32_t*)(WL + off1) = l;
        }
    }
}

// ---------------- fused B+C per (q,bz): 256 thr, 2 CTA/SM (R11 exact) -------
__device__ __forceinline__ void prefB(uint32_t sb, int slot, int k0, int tid,
    const __nv_bfloat16* Xh, const __nv_bfloat16* Xl,
    const __nv_bfloat16* Wh, const __nv_bfloat16* Wl)
{
    if (k0 < Dp) {
        for (int t = tid; t < 1152; t += 256) {
            uint32_t dst; const __nv_bfloat16* g;
            if (t < 512) {
                int img = t >> 8, rr = (t >> 1) & 127, u = t & 1;
                dst = sb + slot * 18432 + img * 4096 + swz(rr, u);
                g = (img ? Xl : Xh) + (size_t)rr * Dp + k0 + u * 8;
            } else {
                int t2 = t - 512;
                int img = t2 / 320, r2 = t2 - img * 320;
                int rr = r2 >> 1, u = r2 & 1;
                dst = sb + slot * 18432 + 8192 + img * 5120 + swz(rr, u);
                g = (img ? Wl : Wh) + (size_t)rr * Dp + k0 + u * 8;
            }
            cpa16(dst, g);
        }
    }
    CP_COMMIT();
}

__global__ void __launch_bounds__(256, 2) k_fusedBC(float* __restrict__ out)
{
    extern __shared__ __align__(16) unsigned char dynsm[];
    uint32_t sb = smem_u32(dynsm);
    int q = blockIdx.y, bz = blockIdx.x, b = bz >> 7, z = bz & 127;
    int tid = threadIdx.x, w = tid >> 5, ln = tid & 31;
    int wm = w & 3, wn = w >> 2;                    // stage B mapping (4x2)
    int tm = (w < 4) ? w : 7 - w, tn = w >> 2;      // stage C mapping (balanced)
    int pb0 = (q == 0) ? 0 : max(0, min(4, 2 * tm - 4 * tn));

    const __nv_bfloat16 *Xh = &g_eh[c_XI[q]][b*128][0], *Xl = &g_el[c_XI[q]][b*128][0];
    const __nv_bfloat16 *Wh = &g_wbh[q][bz][0][0],      *Wl = &g_wbl[q][bz][0][0];
    const __nv_bfloat16 *Yh = &g_eh[c_YI[q]][b*128][0], *Yl = &g_el[c_YI[q]][b*128][0];

    // ---- stage B (warp tile 32x80, k16, 3-slot, 1 sync/iter)
    float accB[2][10][4];
    #pragma unroll
    for (int mt = 0; mt < 2; ++mt)
        #pragma unroll
        for (int i = 0; i < 10; ++i)
            #pragma unroll
            for (int c = 0; c < 4; ++c) accB[mt][i][c] = 0.f;

    prefB(sb, 0, 0,  tid, Xh, Xl, Wh, Wl);
    prefB(sb, 1, 16, tid, Xh, Xl, Wh, Wl);
    for (int ks = 0; ks < 10; ++ks) {
        CP_WAIT1();
        __syncthreads();
        prefB(sb, (ks + 2) % 3, (ks + 2) * 16, tid, Xh, Xl, Wh, Wl);
        uint32_t base = sb + (ks % 3) * 18432;
        uint32_t ah[2][4], al[2][4];
        #pragma unroll
        for (int mt = 0; mt < 2; ++mt) {
            ldsm4(ah[mt], lds_addr(base,        wm * 32 + mt * 16, ln));
            ldsm4(al[mt], lds_addr(base + 4096, wm * 32 + mt * 16, ln));
        }
        #pragma unroll
        for (int p = 0; p < 5; ++p) {
            uint32_t bh[4], bl[4];
            ldsm4(bh, lds_addr(base + 8192,  wn * 80 + p * 16, ln));
            ldsm4(bl, lds_addr(base + 13312, wn * 80 + p * 16, ln));
            MMA_BLK(accB[0][2*p], accB[0][2*p+1], accB[1][2*p], accB[1][2*p+1], ah, al, bh, bl);
        }
    }
    CP_WAIT0();
    __syncthreads();   // stage-B smem reads done; region reused for v images

    // ---- Y chunk prefetch macro (k16 chunks, 3 slots at [81920,106496))
    #define PREF_Y(slot, kc) do { \
        if ((kc) < Dp) { \
            int t = tid; \
            _Pragma("unroll") \
            for (int it = 0; it < 2; ++it, t += 256) { \
                int img = t >> 8, r2 = t & 255; \
                int row = r2 >> 1, u = r2 & 1; \
                cpa16(sb + 81920 + (slot) * 8192 + img * 4096 + swz(row, u), \
                      (img ? Yl : Yh) + (size_t)row * Dp + (kc) + u * 8); \
            } \
        } \
        CP_COMMIT(); \
    } while(0)

    PREF_Y(0, 0);
    PREF_Y(1, 16);

    // ---- v -> split-bf16 smem images at [0,81920)  (hi@0, lo@40960)
    #pragma unroll
    for (int mt = 0; mt < 2; ++mt) {
        #pragma unroll
        for (int n8 = 0; n8 < 10; ++n8) {
            int j  = wn * 80 + n8 * 8 + 2 * (ln & 3);
            int x1 = wm * 32 + mt * 16 + (ln >> 2);
            uint32_t h, l;
            split_pack(accB[mt][n8][0], accB[mt][n8][1], h, l);
            *(uint32_t*)(dynsm + voff(x1, j))         = h;
            *(uint32_t*)(dynsm + 40960 + voff(x1, j)) = l;
            split_pack(accB[mt][n8][2], accB[mt][n8][3], h, l);
            *(uint32_t*)(dynsm + voff(x1 + 8, j))         = h;
            *(uint32_t*)(dynsm + 40960 + voff(x1 + 8, j)) = l;
        }
    }

    // ---- stage C (warp tile 32x64, A from v-images, B from streamed Y)
    float accC[2][8][4];
    #pragma unroll
    for (int mt = 0; mt < 2; ++mt)
        #pragma unroll
        for (int i = 0; i < 8; ++i)
            #pragma unroll
            for (int c = 0; c < 4; ++c) accC[mt][i][c] = 0.f;

    for (int kk = 0; kk < 10; ++kk) {
        CP_WAIT1();
        __syncthreads();          // (first iter also publishes v images)
        PREF_Y((kk + 2) % 3, (kk + 2) * 16);
        uint32_t ybase = sb + 81920 + (kk % 3) * 8192;
        int u0 = kk * 2;
        uint32_t ah[2][4], al[2][4];
        #pragma unroll
        for (int mt = 0; mt < 2; ++mt) {
            ldsm4(ah[mt], ldsV(sb,         tm * 32 + mt * 16, ln, u0));
            ldsm4(al[mt], ldsV(sb + 40960, tm * 32 + mt * 16, ln, u0));
        }
        #pragma unroll
        for (int pb = 0; pb < 4; ++pb) {
            if (pb >= pb0) {
                uint32_t bh[4], bl[4];
                ldsm4(bh, lds_addr(ybase,        tn * 64 + pb * 16, ln));
                ldsm4(bl, lds_addr(ybase + 4096, tn * 64 + pb * 16, ln));
                MMA_BLK(accC[0][2*pb], accC[0][2*pb+1], accC[1][2*pb], accC[1][2*pb+1],
                        ah, al, bh, bl);
            }
        }
    }
    #undef PREF_Y
    CP_WAIT0();
    __syncthreads();   // stage-C smem reads done; reuse region for s-tile

    // ---- epilogue: stage s tile, triu_sym on read, coalesced out
    float* ss = (float*)dynsm;   // [128][130]
    #pragma unroll
    for (int mt = 0; mt < 2; ++mt) {
        int x = tm * 32 + mt * 16 + (ln >> 2);
        #pragma unroll
        for (int nt = 0; nt < 8; ++nt) {
            int y = tn * 64 + nt * 8 + 2 * (ln & 3);
            ss[x * 130 + y]           = accC[mt][nt][0];
            ss[x * 130 + y + 1]       = accC[mt][nt][1];
            ss[(x + 8) * 130 + y]     = accC[mt][nt][2];
            ss[(x + 8) * 130 + y + 1] = accC[mt][nt][3];
        }
    }
    __syncthreads();

    bool dosym = (q != 0);
    float* o;
    if (q < 4) o = out + (size_t)q * 4194304 + (size_t)bz * 16384;
    else       o = &g_cp[(q - 4) * 2 + b][z][0][0];
    int c0 = ln * 4;
    #pragma unroll
    for (int rr = 0; rr < 16; ++rr) {
        int r = w * 16 + rr;
        const float* pr2 = ss + r * 130;
        float4 v;
        v.x = (!dosym || r <= c0    ) ? pr2[c0]     : ss[(c0)     * 130 + r];
        v.y = (!dosym || r <= c0 + 1) ? pr2[c0 + 1] : ss[(c0 + 1) * 130 + r];
        v.z = (!dosym || r <= c0 + 2) ? pr2[c0 + 2] : ss[(c0 + 2) * 130 + r];
        v.w = (!dosym || r <= c0 + 3) ? pr2[c0 + 3] : ss[(c0 + 3) * 130 + r];
        *(float4*)(o + (size_t)r * 128 + c0) = v;
    }
}

// ---------------- co-parent permute: g_cp[t*2+b][z][x][y] -> out[b][x][y][z]
__global__ void k_cop(float* __restrict__ out)
{
    __shared__ float ts[32][33];
    int tile = blockIdx.x;
    int x    = blockIdx.y;
    int tb   = blockIdx.z;
    int z0 = (tile >> 2) * 32, y0 = (tile & 3) * 32;
    int tx = threadIdx.x, ty = threadIdx.y;
    const float* src = &g_cp[tb][0][x][0];
    #pragma unroll
    for (int i = ty; i < 32; i += 8)
        ts[i][tx] = src[(size_t)(z0 + i) * 16384 + y0 + tx];
    __syncthreads();
    float* dst = out + (size_t)(4 + (tb >> 1)) * 4194304 + (size_t)(tb & 1) * 2097152
               + (size_t)x * 16384;
    #pragma unroll
    for (int i = ty; i < 32; i += 8)
        dst[(size_t)(y0 + i) * 128 + z0 + tx] = ts[tx][i];
}

// ---------------------------------------------------------------------------
extern "C" void kernel_launch(void* const* d_in, const int* in_sizes, int n_in,
                              void* d_out, int out_size)
{
    const float* x      = (const float*)d_in[0];
    const float* W_sh   = (const float*)d_in[1];
    const float* b_sh   = (const float*)d_in[2];
    const float* W_st   = (const float*)d_in[3];
    const float* b_st   = (const float*)d_in[4];
    const float* W_p    = (const float*)d_in[5];
    const float* b_p    = (const float*)d_in[6];
    const float* T_pt   = (const float*)d_in[7];
    const float* T_ph   = (const float*)d_in[8];
    const float* T_phsib= (const float*)d_in[9];
    const float* T_ptsib= (const float*)d_in[10];
    const float* T_phcop= (const float*)d_in[11];
    const float* T_ptcop= (const float*)d_in[12];

    static bool attr_done = false;
    if (!attr_done) {
        cudaFuncSetAttribute(k_stageA,  cudaFuncAttributeMaxDynamicSharedMemorySize, 98304);
        cudaFuncSetAttribute(k_fusedBC, cudaFuncAttributeMaxDynamicSharedMemorySize, 106496);
        attr_done = true;
    }

    k_mlp   <<<dim3(3, 64), 160>>>(x, W_sh, b_sh, W_st, b_st, W_p, b_p);
    // q order: 0=T_ph 1=T_pt 2=T_phsib 3=T_ptsib 4=T_phcop 5=T_ptcop
    k_timg  <<<dim3(5, D, 6), 256>>>(T_ph, T_pt, T_phsib, T_ptsib, T_phcop, T_ptcop);
    k_stageA<<<dim3(200, 2, 6), 256, 98304>>>();
    k_fusedBC<<<dim3(BZ, 6), 256, 106496>>>((float*)d_out);
    k_cop   <<<dim3(16, 128, 4), dim3(32, 8)>>>((float*)d_out);
}

// round 14
// speedup vs baseline: 1.2743x; 1.0818x over previous
#include <cuda_runtime.h>
#include <cuda_bf16.h>
#include <cstdint>

#define D      150
#define Dp     160
#define NTOT   25600     // Dp*Dp, n = j*160 + i
#define BZ     256
#define DIN    1024

// ---------------- scratch (__device__ globals; zero-init; pads never written)
__device__ __align__(16) float g_emb[3][BZ][Dp];
__device__ __align__(16) __nv_bfloat16 g_eh[3][BZ][Dp];      // emb hi image
__device__ __align__(16) __nv_bfloat16 g_el[3][BZ][Dp];      // emb lo image
__device__ __align__(16) __nv_bfloat16 g_tbh[6][NTOT][Dp];   // T image [q][n][k] hi
__device__ __align__(16) __nv_bfloat16 g_tbl[6][NTOT][Dp];   // lo
__device__ __align__(16) __nv_bfloat16 g_wbh[6][BZ][Dp][Dp]; // w image [q][bz][j][i] hi
__device__ __align__(16) __nv_bfloat16 g_wbl[6][BZ][Dp][Dp]; // lo
__device__ __align__(16) float g_cp[4][128][128][128];       // co-parent staging

// q0 span_psh (no sym)  q1 span_pst (sym)  q2 ph_sib  q3 pt_sib
// q4 ph_cop  q5 pt_cop  (q4,q5 permuted out via g_cp + k_cop)
__constant__ int c_ZI[6] = {2,2,2,2,0,1};
__constant__ int c_XI[6] = {0,0,0,1,2,2};
__constant__ int c_YI[6] = {1,1,0,1,2,2};

// ---------------- low-level helpers ----------------------------------------
__device__ __forceinline__ uint32_t smem_u32(const void* p){
    uint32_t a;
    asm("{ .reg .u64 t; cvta.to.shared.u64 t, %1; cvt.u32.u64 %0, t; }" : "=r"(a) : "l"(p));
    return a;
}
__device__ __forceinline__ void split_pack(float a, float b, uint32_t& h, uint32_t& l){
    __nv_bfloat16 ah = __float2bfloat16(a), bh = __float2bfloat16(b);
    __nv_bfloat16 al = __float2bfloat16(a - __bfloat162float(ah));
    __nv_bfloat16 bl = __float2bfloat16(b - __bfloat162float(bh));
    h = (uint32_t)__bfloat16_as_ushort(ah) | ((uint32_t)__bfloat16_as_ushort(bh) << 16);
    l = (uint32_t)__bfloat16_as_ushort(al) | ((uint32_t)__bfloat16_as_ushort(bl) << 16);
}
__device__ __forceinline__ void mma16816(float* c, const uint32_t* a, uint32_t b0, uint32_t b1){
    asm volatile("mma.sync.aligned.m16n8k16.row.col.f32.bf16.bf16.f32 "
        "{%0,%1,%2,%3}, {%4,%5,%6,%7}, {%8,%9}, {%0,%1,%2,%3};"
        : "+f"(c[0]), "+f"(c[1]), "+f"(c[2]), "+f"(c[3])
        : "r"(a[0]), "r"(a[1]), "r"(a[2]), "r"(a[3]), "r"(b0), "r"(b1));
}
__device__ __forceinline__ void ldsm4(uint32_t* r, uint32_t a){
    asm volatile("ldmatrix.sync.aligned.m8n8.x4.shared.b16 {%0,%1,%2,%3}, [%4];"
        : "=r"(r[0]), "=r"(r[1]), "=r"(r[2]), "=r"(r[3]) : "r"(a));
}
__device__ __forceinline__ void cpa16(uint32_t s, const void* g){
    asm volatile("cp.async.cg.shared.global [%0], [%1], 16;" :: "r"(s), "l"(g));
}
#define CP_COMMIT() asm volatile("cp.async.commit_group;" ::: "memory")
#define CP_WAIT1()  asm volatile("cp.async.wait_group 1;" ::: "memory")
#define CP_WAIT0()  asm volatile("cp.async.wait_group 0;" ::: "memory")

// 32B-row layout (k16 chunks): 2x16B units/row, XOR swizzle (R7-proven)
__device__ __forceinline__ uint32_t swz(int row, int u){
    return (uint32_t)(row * 32 + (((u ^ (row >> 2)) & 1) << 4));
}
__device__ __forceinline__ uint32_t lds_addr(uint32_t base, int r0, int ln){
    int g = ln >> 3;
    int row = r0 + ((g & 1) << 3) + (ln & 7);
    return base + swz(row, g >> 1);
}
// 64B-row layout (k32 chunks), R9-proven
__device__ __forceinline__ uint32_t swz64(int row, int u){
    return (uint32_t)(row * 64 + 16 * ((u ^ (row >> 1)) & 3));
}
__device__ __forceinline__ uint32_t a64(uint32_t base, int r0, int ln, int c){
    int g = ln >> 3;
    int row = r0 + ((g & 1) << 3) + (ln & 7);
    return base + swz64(row, 2 * c + (g >> 1));
}
// 320B-row image layout (v), R7-proven
__device__ __forceinline__ uint32_t voff(int row, int j){
    return (uint32_t)(row * 320 + 16 * ((j >> 3) ^ ((row >> 1) & 3)) + (j & 7) * 2);
}
__device__ __forceinline__ uint32_t vuoff(int row, int u){
    return (uint32_t)(row * 320 + 16 * (u ^ ((row >> 1) & 3)));
}
__device__ __forceinline__ uint32_t ldsV(uint32_t base, int r0, int ln, int u0){
    int g = ln >> 3;
    int row = r0 + ((g & 1) << 3) + (ln & 7);
    return base + vuoff(row, u0 + (g >> 1));
}
// ILP-4 split-major 12-MMA block
#define MMA_BLK(t00, t01, t10, t11, ah, al, bh, bl) do { \
    mma16816(t00, ah[0], bh[0], bh[2]); \
    mma16816(t01, ah[0], bh[1], bh[3]); \
    mma16816(t10, ah[1], bh[0], bh[2]); \
    mma16816(t11, ah[1], bh[1], bh[3]); \
    mma16816(t00, ah[0], bl[0], bl[2]); \
    mma16816(t01, ah[0], bl[1], bl[3]); \
    mma16816(t10, ah[1], bl[0], bl[2]); \
    mma16816(t11, ah[1], bl[1], bl[3]); \
    mma16816(t00, al[0], bh[0], bh[2]); \
    mma16816(t01, al[0], bh[1], bh[3]); \
    mma16816(t10, al[1], bh[0], bh[2]); \
    mma16816(t11, al[1], bh[1], bh[3]); \
} while(0)

// ---------------- MLP (R11-original: one block per (row,e)) -----------------
__global__ void k_mlp(const float* __restrict__ x,
                      const float* __restrict__ W0, const float* __restrict__ b0,
                      const float* __restrict__ W1, const float* __restrict__ b1,
                      const float* __restrict__ W2, const float* __restrict__ b2)
{
    int row = blockIdx.x, e = blockIdx.y;
    const float* W  = (e == 0) ? W0 : (e == 1) ? W1 : W2;
    const float* bb = (e == 0) ? b0 : (e == 1) ? b1 : b2;
    __shared__ float xs[DIN];
    int tid = threadIdx.x;
    for (int k = tid; k < DIN; k += 160) xs[k] = x[row * DIN + k];
    __syncthreads();
    if (tid < D) {
        float acc = bb[tid];
        #pragma unroll 8
        for (int k = 0; k < DIN; ++k) acc += xs[k] * W[k * D + tid];
        g_emb[e][row][tid] = (acc >= 0.f) ? acc : 0.1f * acc;
    }
}

// ---------------- emb -> split bf16 images ---------------------------------
__global__ void k_embimg()
{
    int idx = blockIdx.x * 256 + threadIdx.x;
    if (idx >= 3 * 256 * 80) return;
    int e = idx / 20480, rem = idx % 20480;
    int row = rem / 80, kp = rem % 80;
    uint32_t h, l;
    split_pack(g_emb[e][row][2*kp], g_emb[e][row][2*kp+1], h, l);
    *(uint32_t*)&g_eh[e][row][2*kp] = h;
    *(uint32_t*)&g_el[e][row][2*kp] = l;
}

// ---------------- T[i][k][j] -> TB[q][(j*160+i)][k] hi/lo -------------------
__global__ void k_timg(const float* __restrict__ T0, const float* __restrict__ T1,
                       const float* __restrict__ T2, const float* __restrict__ T3,
                       const float* __restrict__ T4, const float* __restrict__ T5)
{
    int q = blockIdx.z, i = blockIdx.y, j0 = blockIdx.x * 32;
    const float* T = (q==0)?T0:(q==1)?T1:(q==2)?T2:(q==3)?T3:(q==4)?T4:T5;
    __shared__ float ts[32][152];
    int tid = threadIdx.x;
    for (int t = tid; t < 150 * 32; t += 256) {
        int k = t >> 5, j = t & 31;
        if (j0 + j < D) ts[j][k] = T[(i * D + k) * D + j0 + j];
    }
    __syncthreads();
    for (int t = tid; t < 32 * 75; t += 256) {
        int j = t / 75, kp = t % 75;
        if (j0 + j < D) {
            uint32_t h, l;
            split_pack(ts[j][2*kp], ts[j][2*kp+1], h, l);
            int n = (j0 + j) * Dp + i;
            *(uint32_t*)&g_tbh[q][n][2*kp] = h;
            *(uint32_t*)&g_tbl[q][n][2*kp] = l;
        }
    }
}

// ---------------- stage A: w = Z . TB^T, k32 chunks (R9 exact; 188 N-tiles) -
// N-tiles 188..199 cover n >= 24064 where Tt rows (j >= 150) are all-zero:
// outputs there are zeros that static zero-init of g_wb already provides.
__global__ void __launch_bounds__(256, 2) k_stageA()
{
    extern __shared__ __align__(16) unsigned char smA[];   // 3 x 32768
    uint32_t sb = smem_u32(smA);
    int q = blockIdx.z, m0 = blockIdx.y * 128, n0 = blockIdx.x * 128;
    int tid = threadIdx.x, w = tid >> 5, ln = tid & 31;
    int wm = w & 3, wn = w >> 2;
    int zi = c_ZI[q];

    int pr = tid >> 2, pu = tid & 3;
    uint32_t sw0 = swz64(pr, pu);
    const __nv_bfloat16* gpA[4];
    gpA[0] = &g_eh[zi][0][0]  + (size_t)(m0 + pr) * Dp + pu * 8;
    gpA[1] = &g_el[zi][0][0]  + (size_t)(m0 + pr) * Dp + pu * 8;
    gpA[2] = &g_tbh[q][0][0]  + (size_t)(n0 + pr) * Dp + pu * 8;
    gpA[3] = &g_tbl[q][0][0]  + (size_t)(n0 + pr) * Dp + pu * 8;

    float acc[2][8][4];
    #pragma unroll
    for (int a = 0; a < 2; ++a)
        #pragma unroll
        for (int b = 0; b < 8; ++b)
            #pragma unroll
            for (int c = 0; c < 4; ++c) acc[a][b][c] = 0.f;

    #define PREF_A(slot, kc) do { \
        if ((kc) < Dp) { \
            uint32_t db = sb + (slot) * 32768 + sw0; \
            _Pragma("unroll") \
            for (int a = 0; a < 4; ++a) { \
                cpa16(db + a * 8192,        gpA[a] + (kc)); \
                cpa16(db + a * 8192 + 4096, gpA[a] + 64 * Dp + (kc)); \
            } \
        } \
        CP_COMMIT(); \
    } while(0)

    PREF_A(0, 0);
    PREF_A(1, 32);
    for (int ks = 0; ks < 5; ++ks) {
        CP_WAIT1();
        __syncthreads();
        PREF_A((ks + 2) % 3, (ks + 2) * 32);
        uint32_t base = sb + (ks % 3) * 32768;
        #pragma unroll
        for (int c = 0; c < 2; ++c) {
            uint32_t ah[2][4], al[2][4];
            #pragma unroll
            for (int mt = 0; mt < 2; ++mt) {
                ldsm4(ah[mt], a64(base,        wm * 32 + mt * 16, ln, c));
                ldsm4(al[mt], a64(base + 8192, wm * 32 + mt * 16, ln, c));
            }
            #pragma unroll
            for (int p = 0; p < 4; ++p) {
                uint32_t bh[4], bl[4];
                ldsm4(bh, a64(base + 16384, wn * 64 + p * 16, ln, c));
                ldsm4(bl, a64(base + 24576, wn * 64 + p * 16, ln, c));
                MMA_BLK(acc[0][2*p], acc[0][2*p+1], acc[1][2*p], acc[1][2*p+1], ah, al, bh, bl);
            }
        }
    }
    #undef PREF_A

    __nv_bfloat16* WH = &g_wbh[0][0][0][0];
    __nv_bfloat16* WL = &g_wbl[0][0][0][0];
    int yb = 2 * (ln & 3);
    #pragma unroll
    for (int mt = 0; mt < 2; ++mt) {
        int mA = m0 + wm * 32 + mt * 16 + (ln >> 2);
        #pragma unroll
        for (int nt = 0; nt < 8; ++nt) {
            int n = n0 + wn * 64 + nt * 8 + yb;
            size_t off0 = ((size_t)(q * BZ + mA)) * 25600 + n;
            size_t off1 = off0 + (size_t)8 * 25600;
            uint32_t h, l;
            split_pack(acc[mt][nt][0], acc[mt][nt][1], h, l);
            *(uint32_t*)(WH + off0) = h; *(uint32_t*)(WL + off0) = l;
            split_pack(acc[mt][nt][2], acc[mt][nt][3], h, l);
            *(uint32_t*)(WH + off1) = h; *(uint32_t*)(WL + off1) = l;
        }
    }
}

// ---------------- fused B+C per (q,bz): 256 thr, 2 CTA/SM (R11 exact) -------
__device__ __forceinline__ void prefB(uint32_t sb, int slot, int k0, int tid,
    const __nv_bfloat16* Xh, const __nv_bfloat16* Xl,
    const __nv_bfloat16* Wh, const __nv_bfloat16* Wl)
{
    if (k0 < Dp) {
        for (int t = tid; t < 1152; t += 256) {
            uint32_t dst; const __nv_bfloat16* g;
            if (t < 512) {
                int img = t >> 8, rr = (t >> 1) & 127, u = t & 1;
                dst = sb + slot * 18432 + img * 4096 + swz(rr, u);
                g = (img ? Xl : Xh) + (size_t)rr * Dp + k0 + u * 8;
            } else {
                int t2 = t - 512;
                int img = t2 / 320, r2 = t2 - img * 320;
                int rr = r2 >> 1, u = r2 & 1;
                dst = sb + slot * 18432 + 8192 + img * 5120 + swz(rr, u);
                g = (img ? Wl : Wh) + (size_t)rr * Dp + k0 + u * 8;
            }
            cpa16(dst, g);
        }
    }
    CP_COMMIT();
}

__global__ void __launch_bounds__(256, 2) k_fusedBC(float* __restrict__ out)
{
    extern __shared__ __align__(16) unsigned char dynsm[];
    uint32_t sb = smem_u32(dynsm);
    int q = blockIdx.y, bz = blockIdx.x, b = bz >> 7, z = bz & 127;
    int tid = threadIdx.x, w = tid >> 5, ln = tid & 31;
    int wm = w & 3, wn = w >> 2;                    // stage B mapping (4x2)
    int tm = (w < 4) ? w : 7 - w, tn = w >> 2;      // stage C mapping (balanced)
    int pb0 = (q == 0) ? 0 : max(0, min(4, 2 * tm - 4 * tn));

    const __nv_bfloat16 *Xh = &g_eh[c_XI[q]][b*128][0], *Xl = &g_el[c_XI[q]][b*128][0];
    const __nv_bfloat16 *Wh = &g_wbh[q][bz][0][0],      *Wl = &g_wbl[q][bz][0][0];
    const __nv_bfloat16 *Yh = &g_eh[c_YI[q]][b*128][0], *Yl = &g_el[c_YI[q]][b*128][0];

    // ---- stage B (warp tile 32x80, k16, 3-slot, 1 sync/iter)
    float accB[2][10][4];
    #pragma unroll
    for (int mt = 0; mt < 2; ++mt)
        #pragma unroll
        for (int i = 0; i < 10; ++i)
            #pragma unroll
            for (int c = 0; c < 4; ++c) accB[mt][i][c] = 0.f;

    prefB(sb, 0, 0,  tid, Xh, Xl, Wh, Wl);
    prefB(sb, 1, 16, tid, Xh, Xl, Wh, Wl);
    for (int ks = 0; ks < 10; ++ks) {
        CP_WAIT1();
        __syncthreads();
        prefB(sb, (ks + 2) % 3, (ks + 2) * 16, tid, Xh, Xl, Wh, Wl);
        uint32_t base = sb + (ks % 3) * 18432;
        uint32_t ah[2][4], al[2][4];
        #pragma unroll
        for (int mt = 0; mt < 2; ++mt) {
            ldsm4(ah[mt], lds_addr(base,        wm * 32 + mt * 16, ln));
            ldsm4(al[mt], lds_addr(base + 4096, wm * 32 + mt * 16, ln));
        }
        #pragma unroll
        for (int p = 0; p < 5; ++p) {
            uint32_t bh[4], bl[4];
            ldsm4(bh, lds_addr(base + 8192,  wn * 80 + p * 16, ln));
            ldsm4(bl, lds_addr(base + 13312, wn * 80 + p * 16, ln));
            MMA_BLK(accB[0][2*p], accB[0][2*p+1], accB[1][2*p], accB[1][2*p+1], ah, al, bh, bl);
        }
    }
    CP_WAIT0();
    __syncthreads();   // stage-B smem reads done; region reused for v images

    // ---- Y chunk prefetch macro (k16 chunks, 3 slots at [81920,106496))
    #define PREF_Y(slot, kc) do { \
        if ((kc) < Dp) { \
            int t = tid; \
            _Pragma("unroll") \
            for (int it = 0; it < 2; ++it, t += 256) { \
                int img = t >> 8, r2 = t & 255; \
                int row = r2 >> 1, u = r2 & 1; \
                cpa16(sb + 81920 + (slot) * 8192 + img * 4096 + swz(row, u), \
                      (img ? Yl : Yh) + (size_t)row * Dp + (kc) + u * 8); \
            } \
        } \
        CP_COMMIT(); \
    } while(0)

    PREF_Y(0, 0);
    PREF_Y(1, 16);

    // ---- v -> split-bf16 smem images at [0,81920)  (hi@0, lo@40960)
    #pragma unroll
    for (int mt = 0; mt < 2; ++mt) {
        #pragma unroll
        for (int n8 = 0; n8 < 10; ++n8) {
            int j  = wn * 80 + n8 * 8 + 2 * (ln & 3);
            int x1 = wm * 32 + mt * 16 + (ln >> 2);
            uint32_t h, l;
            split_pack(accB[mt][n8][0], accB[mt][n8][1], h, l);
            *(uint32_t*)(dynsm + voff(x1, j))         = h;
            *(uint32_t*)(dynsm + 40960 + voff(x1, j)) = l;
            split_pack(accB[mt][n8][2], accB[mt][n8][3], h, l);
            *(uint32_t*)(dynsm + voff(x1 + 8, j))         = h;
            *(uint32_t*)(dynsm + 40960 + voff(x1 + 8, j)) = l;
        }
    }

    // ---- stage C (warp tile 32x64, A from v-images, B from streamed Y)
    float accC[2][8][4];
    #pragma unroll
    for (int mt = 0; mt < 2; ++mt)
        #pragma unroll
        for (int i = 0; i < 8; ++i)
            #pragma unroll
            for (int c = 0; c < 4; ++c) accC[mt][i][c] = 0.f;

    for (int kk = 0; kk < 10; ++kk) {
        CP_WAIT1();
        __syncthreads();          // (first iter also publishes v images)
        PREF_Y((kk + 2) % 3, (kk + 2) * 16);
        uint32_t ybase = sb + 81920 + (kk % 3) * 8192;
        int u0 = kk * 2;
        uint32_t ah[2][4], al[2][4];
        #pragma unroll
        for (int mt = 0; mt < 2; ++mt) {
            ldsm4(ah[mt], ldsV(sb,         tm * 32 + mt * 16, ln, u0));
            ldsm4(al[mt], ldsV(sb + 40960, tm * 32 + mt * 16, ln, u0));
        }
        #pragma unroll
        for (int pb = 0; pb < 4; ++pb) {
            if (pb >= pb0) {
                uint32_t bh[4], bl[4];
                ldsm4(bh, lds_addr(ybase,        tn * 64 + pb * 16, ln));
                ldsm4(bl, lds_addr(ybase + 4096, tn * 64 + pb * 16, ln));
                MMA_BLK(accC[0][2*pb], accC[0][2*pb+1], accC[1][2*pb], accC[1][2*pb+1],
                        ah, al, bh, bl);
            }
        }
    }
    #undef PREF_Y
    CP_WAIT0();
    __syncthreads();   // stage-C smem reads done; reuse region for s-tile

    // ---- epilogue: stage s tile, triu_sym on read, coalesced out
    float* ss = (float*)dynsm;   // [128][130]
    #pragma unroll
    for (int mt = 0; mt < 2; ++mt) {
        int x = tm * 32 + mt * 16 + (ln >> 2);
        #pragma unroll
        for (int nt = 0; nt < 8; ++nt) {
            int y = tn * 64 + nt * 8 + 2 * (ln & 3);
            ss[x * 130 + y]           = accC[mt][nt][0];
            ss[x * 130 + y + 1]       = accC[mt][nt][1];
            ss[(x + 8) * 130 + y]     = accC[mt][nt][2];
            ss[(x + 8) * 130 + y + 1] = accC[mt][nt][3];
        }
    }
    __syncthreads();

    bool dosym = (q != 0);
    float* o;
    if (q < 4) o = out + (size_t)q * 4194304 + (size_t)bz * 16384;
    else       o = &g_cp[(q - 4) * 2 + b][z][0][0];
    int c0 = ln * 4;
    #pragma unroll
    for (int rr = 0; rr < 16; ++rr) {
        int r = w * 16 + rr;
        const float* pr2 = ss + r * 130;
        float4 v;
        v.x = (!dosym || r <= c0    ) ? pr2[c0]     : ss[(c0)     * 130 + r];
        v.y = (!dosym || r <= c0 + 1) ? pr2[c0 + 1] : ss[(c0 + 1) * 130 + r];
        v.z = (!dosym || r <= c0 + 2) ? pr2[c0 + 2] : ss[(c0 + 2) * 130 + r];
        v.w = (!dosym || r <= c0 + 3) ? pr2[c0 + 3] : ss[(c0 + 3) * 130 + r];
        *(float4*)(o + (size_t)r * 128 + c0) = v;
    }
}

// ---------------- co-parent permute: g_cp[t*2+b][z][x][y] -> out[b][x][y][z]
__global__ void k_cop(float* __restrict__ out)
{
    __shared__ float ts[32][33];
    int tile = blockIdx.x;
    int x    = blockIdx.y;
    int tb   = blockIdx.z;
    int z0 = (tile >> 2) * 32, y0 = (tile & 3) * 32;
    int tx = threadIdx.x, ty = threadIdx.y;
    const float* src = &g_cp[tb][0][x][0];
    #pragma unroll
    for (int i = ty; i < 32; i += 8)
        ts[i][tx] = src[(size_t)(z0 + i) * 16384 + y0 + tx];
    __syncthreads();
    float* dst = out + (size_t)(4 + (tb >> 1)) * 4194304 + (size_t)(tb & 1) * 2097152
               + (size_t)x * 16384;
    #pragma unroll
    for (int i = ty; i < 32; i += 8)
        dst[(size_t)(y0 + i) * 128 + z0 + tx] = ts[tx][i];
}

// ---------------------------------------------------------------------------
extern "C" void kernel_launch(void* const* d_in, const int* in_sizes, int n_in,
                              void* d_out, int out_size)
{
    const float* x      = (const float*)d_in[0];
    const float* W_sh   = (const float*)d_in[1];
    const float* b_sh   = (const float*)d_in[2];
    const float* W_st   = (const float*)d_in[3];
    const float* b_st   = (const float*)d_in[4];
    const float* W_p    = (const float*)d_in[5];
    const float* b_p    = (const float*)d_in[6];
    const float* T_pt   = (const float*)d_in[7];
    const float* T_ph   = (const float*)d_in[8];
    const float* T_phsib= (const float*)d_in[9];
    const float* T_ptsib= (const float*)d_in[10];
    const float* T_phcop= (const float*)d_in[11];
    const float* T_ptcop= (const float*)d_in[12];

    static bool attr_done = false;
    if (!attr_done) {
        cudaFuncSetAttribute(k_stageA,  cudaFuncAttributeMaxDynamicSharedMemorySize, 98304);
        cudaFuncSetAttribute(k_fusedBC, cudaFuncAttributeMaxDynamicSharedMemorySize, 106496);
        attr_done = true;
    }

    k_mlp   <<<dim3(BZ, 3), 160>>>(x, W_sh, b_sh, W_st, b_st, W_p, b_p);
    k_embimg<<<240, 256>>>();
    // q order: 0=T_ph 1=T_pt 2=T_phsib 3=T_ptsib 4=T_phcop 5=T_ptcop
    k_timg  <<<dim3(5, D, 6), 256>>>(T_ph, T_pt, T_phsib, T_ptsib, T_phcop, T_ptcop);
    k_stageA<<<dim3(188, 2, 6), 256, 98304>>>();
    k_fusedBC<<<dim3(BZ, 6), 256, 106496>>>((float*)d_out);
    k_cop   <<<dim3(16, 128, 4), dim3(32, 8)>>>((float*)d_out);
}

// round 15
// speedup vs baseline: 1.3956x; 1.0952x over previous
#include <cuda_runtime.h>
#include <cuda_bf16.h>
#include <cstdint>

#define D      150
#define Dp     160
#define NTOT   25600     // Dp*Dp, n = j*160 + i
#define BZ     256
#define DIN    1024

// ---------------- scratch (__device__ globals; zero-init; pads never written)
__device__ __align__(16) float g_part[3][8][BZ][Dp];         // mlp split-K partials
__device__ __align__(16) __nv_bfloat16 g_eh[3][BZ][Dp];      // emb hi image
__device__ __align__(16) __nv_bfloat16 g_el[3][BZ][Dp];      // emb lo image
__device__ __align__(16) __nv_bfloat16 g_tbh[6][NTOT][Dp];   // T image [q][n][k] hi
__device__ __align__(16) __nv_bfloat16 g_tbl[6][NTOT][Dp];   // lo
__device__ __align__(16) __nv_bfloat16 g_wbh[6][BZ][Dp][Dp]; // w image [q][bz][j][i] hi
__device__ __align__(16) __nv_bfloat16 g_wbl[6][BZ][Dp][Dp]; // lo
__device__ __align__(16) float g_cp[4][128][128][128];       // co-parent staging

// q0 span_psh (no sym)  q1 span_pst (sym)  q2 ph_sib  q3 pt_sib
// q4 ph_cop  q5 pt_cop  (q4,q5 permuted out via g_cp + k_cop)
__constant__ int c_ZI[6] = {2,2,2,2,0,1};
__constant__ int c_XI[6] = {0,0,0,1,2,2};
__constant__ int c_YI[6] = {1,1,0,1,2,2};

// ---------------- low-level helpers ----------------------------------------
__device__ __forceinline__ uint32_t smem_u32(const void* p){
    uint32_t a;
    asm("{ .reg .u64 t; cvta.to.shared.u64 t, %1; cvt.u32.u64 %0, t; }" : "=r"(a) : "l"(p));
    return a;
}
__device__ __forceinline__ void split_pack(float a, float b, uint32_t& h, uint32_t& l){
    __nv_bfloat16 ah = __float2bfloat16(a), bh = __float2bfloat16(b);
    __nv_bfloat16 al = __float2bfloat16(a - __bfloat162float(ah));
    __nv_bfloat16 bl = __float2bfloat16(b - __bfloat162float(bh));
    h = (uint32_t)__bfloat16_as_ushort(ah) | ((uint32_t)__bfloat16_as_ushort(bh) << 16);
    l = (uint32_t)__bfloat16_as_ushort(al) | ((uint32_t)__bfloat16_as_ushort(bl) << 16);
}
__device__ __forceinline__ void mma16816(float* c, const uint32_t* a, uint32_t b0, uint32_t b1){
    asm volatile("mma.sync.aligned.m16n8k16.row.col.f32.bf16.bf16.f32 "
        "{%0,%1,%2,%3}, {%4,%5,%6,%7}, {%8,%9}, {%0,%1,%2,%3};"
        : "+f"(c[0]), "+f"(c[1]), "+f"(c[2]), "+f"(c[3])
        : "r"(a[0]), "r"(a[1]), "r"(a[2]), "r"(a[3]), "r"(b0), "r"(b1));
}
__device__ __forceinline__ void ldsm4(uint32_t* r, uint32_t a){
    asm volatile("ldmatrix.sync.aligned.m8n8.x4.shared.b16 {%0,%1,%2,%3}, [%4];"
        : "=r"(r[0]), "=r"(r[1]), "=r"(r[2]), "=r"(r[3]) : "r"(a));
}
__device__ __forceinline__ void cpa16(uint32_t s, const void* g){
    asm volatile("cp.async.cg.shared.global [%0], [%1], 16;" :: "r"(s), "l"(g));
}
#define CP_COMMIT() asm volatile("cp.async.commit_group;" ::: "memory")
#define CP_WAIT1()  asm volatile("cp.async.wait_group 1;" ::: "memory")
#define CP_WAIT0()  asm volatile("cp.async.wait_group 0;" ::: "memory")

// 32B-row layout (k16 chunks): 2x16B units/row, XOR swizzle (R7-proven)
__device__ __forceinline__ uint32_t swz(int row, int u){
    return (uint32_t)(row * 32 + (((u ^ (row >> 2)) & 1) << 4));
}
__device__ __forceinline__ uint32_t lds_addr(uint32_t base, int r0, int ln){
    int g = ln >> 3;
    int row = r0 + ((g & 1) << 3) + (ln & 7);
    return base + swz(row, g >> 1);
}
// 64B-row layout (k32 chunks), R9-proven
__device__ __forceinline__ uint32_t swz64(int row, int u){
    return (uint32_t)(row * 64 + 16 * ((u ^ (row >> 1)) & 3));
}
__device__ __forceinline__ uint32_t a64(uint32_t base, int r0, int ln, int c){
    int g = ln >> 3;
    int row = r0 + ((g & 1) << 3) + (ln & 7);
    return base + swz64(row, 2 * c + (g >> 1));
}
// 320B-row image layout (v), R7-proven
__device__ __forceinline__ uint32_t voff(int row, int j){
    return (uint32_t)(row * 320 + 16 * ((j >> 3) ^ ((row >> 1) & 3)) + (j & 7) * 2);
}
__device__ __forceinline__ uint32_t vuoff(int row, int u){
    return (uint32_t)(row * 320 + 16 * (u ^ ((row >> 1) & 3)));
}
__device__ __forceinline__ uint32_t ldsV(uint32_t base, int r0, int ln, int u0){
    int g = ln >> 3;
    int row = r0 + ((g & 1) << 3) + (ln & 7);
    return base + vuoff(row, u0 + (g >> 1));
}
// ILP-4 split-major 12-MMA block
#define MMA_BLK(t00, t01, t10, t11, ah, al, bh, bl) do { \
    mma16816(t00, ah[0], bh[0], bh[2]); \
    mma16816(t01, ah[0], bh[1], bh[3]); \
    mma16816(t10, ah[1], bh[0], bh[2]); \
    mma16816(t11, ah[1], bh[1], bh[3]); \
    mma16816(t00, ah[0], bl[0], bl[2]); \
    mma16816(t01, ah[0], bl[1], bl[3]); \
    mma16816(t10, ah[1], bl[0], bl[2]); \
    mma16816(t11, ah[1], bl[1], bl[3]); \
    mma16816(t00, al[0], bh[0], bh[2]); \
    mma16816(t01, al[0], bh[1], bh[3]); \
    mma16816(t10, al[1], bh[0], bh[2]); \
    mma16816(t11, al[1], bh[1], bh[3]); \
} while(0)

// ---------------- MLP split-K partials ---------------------------------------
// grid (3 e, 8 kslice, 16 rowblk), 160 thr. Each block: 16 rows x 150 cols x
// 128 k. W slice read once per block: total W traffic 471 -> 29 MB.
__global__ void k_mlp_part(const float* __restrict__ x,
                           const float* __restrict__ W0,
                           const float* __restrict__ W1,
                           const float* __restrict__ W2)
{
    int e = blockIdx.x, ks = blockIdx.y, r0 = blockIdx.z * 16;
    const float* W = (e == 0) ? W0 : (e == 1) ? W1 : W2;
    __shared__ float xs[16][128];
    int tid = threadIdx.x;     // 0..159
    for (int i = tid; i < 16 * 128; i += 160) {
        int r = i >> 7, k = i & 127;
        xs[r][k] = x[(size_t)(r0 + r) * DIN + ks * 128 + k];
    }
    __syncthreads();
    if (tid < D) {
        float acc[16];
        #pragma unroll
        for (int r = 0; r < 16; ++r) acc[r] = 0.f;
        #pragma unroll 4
        for (int k = 0; k < 128; ++k) {
            float wv = W[(size_t)(ks * 128 + k) * D + tid];
            #pragma unroll
            for (int r = 0; r < 16; ++r) acc[r] += xs[r][k] * wv;
        }
        #pragma unroll
        for (int r = 0; r < 16; ++r)
            g_part[e][ks][r0 + r][tid] = acc[r];
    }
}

// ---------------- finalize: bias + sum partials -> leaky -> split images ----
__global__ void k_fin(const float* __restrict__ b0,
                      const float* __restrict__ b1,
                      const float* __restrict__ b2)
{
    int idx = blockIdx.x * 256 + threadIdx.x;      // 3*256*80
    if (idx >= 3 * 256 * 80) return;
    int e = idx / 20480, rem = idx % 20480;
    int row = rem / 80, kp = rem % 80;
    const float* bb = (e == 0) ? b0 : (e == 1) ? b1 : b2;
    int c0 = 2 * kp, c1 = 2 * kp + 1;
    float v0 = 0.f, v1 = 0.f;
    if (c0 < D) {
        v0 = bb[c0];
        #pragma unroll
        for (int ks = 0; ks < 8; ++ks) v0 += g_part[e][ks][row][c0];
        v0 = (v0 >= 0.f) ? v0 : 0.1f * v0;
    }
    if (c1 < D) {
        v1 = bb[c1];
        #pragma unroll
        for (int ks = 0; ks < 8; ++ks) v1 += g_part[e][ks][row][c1];
        v1 = (v1 >= 0.f) ? v1 : 0.1f * v1;
    }
    uint32_t h, l;
    split_pack(v0, v1, h, l);
    *(uint32_t*)&g_eh[e][row][c0] = h;
    *(uint32_t*)&g_el[e][row][c0] = l;
}

// ---------------- T[i][k][j] -> TB[q][(j*160+i)][k] hi/lo -------------------
__global__ void k_timg(const float* __restrict__ T0, const float* __restrict__ T1,
                       const float* __restrict__ T2, const float* __restrict__ T3,
                       const float* __restrict__ T4, const float* __restrict__ T5)
{
    int q = blockIdx.z, i = blockIdx.y, j0 = blockIdx.x * 32;
    const float* T = (q==0)?T0:(q==1)?T1:(q==2)?T2:(q==3)?T3:(q==4)?T4:T5;
    __shared__ float ts[32][152];
    int tid = threadIdx.x;
    for (int t = tid; t < 150 * 32; t += 256) {
        int k = t >> 5, j = t & 31;
        if (j0 + j < D) ts[j][k] = T[(i * D + k) * D + j0 + j];
    }
    __syncthreads();
    for (int t = tid; t < 32 * 75; t += 256) {
        int j = t / 75, kp = t % 75;
        if (j0 + j < D) {
            uint32_t h, l;
            split_pack(ts[j][2*kp], ts[j][2*kp+1], h, l);
            int n = (j0 + j) * Dp + i;
            *(uint32_t*)&g_tbh[q][n][2*kp] = h;
            *(uint32_t*)&g_tbl[q][n][2*kp] = l;
        }
    }
}

// ---------------- stage A: w = Z . TB^T, k32 chunks (R14 exact; 188 N-tiles)
__global__ void __launch_bounds__(256, 2) k_stageA()
{
    extern __shared__ __align__(16) unsigned char smA[];   // 3 x 32768
    uint32_t sb = smem_u32(smA);
    int q = blockIdx.z, m0 = blockIdx.y * 128, n0 = blockIdx.x * 128;
    int tid = threadIdx.x, w = tid >> 5, ln = tid & 31;
    int wm = w & 3, wn = w >> 2;
    int zi = c_ZI[q];

    int pr = tid >> 2, pu = tid & 3;
    uint32_t sw0 = swz64(pr, pu);
    const __nv_bfloat16* gpA[4];
    gpA[0] = &g_eh[zi][0][0]  + (size_t)(m0 + pr) * Dp + pu * 8;
    gpA[1] = &g_el[zi][0][0]  + (size_t)(m0 + pr) * Dp + pu * 8;
    gpA[2] = &g_tbh[q][0][0]  + (size_t)(n0 + pr) * Dp + pu * 8;
    gpA[3] = &g_tbl[q][0][0]  + (size_t)(n0 + pr) * Dp + pu * 8;

    float acc[2][8][4];
    #pragma unroll
    for (int a = 0; a < 2; ++a)
        #pragma unroll
        for (int b = 0; b < 8; ++b)
            #pragma unroll
            for (int c = 0; c < 4; ++c) acc[a][b][c] = 0.f;

    #define PREF_A(slot, kc) do { \
        if ((kc) < Dp) { \
            uint32_t db = sb + (slot) * 32768 + sw0; \
            _Pragma("unroll") \
            for (int a = 0; a < 4; ++a) { \
                cpa16(db + a * 8192,        gpA[a] + (kc)); \
                cpa16(db + a * 8192 + 4096, gpA[a] + 64 * Dp + (kc)); \
            } \
        } \
        CP_COMMIT(); \
    } while(0)

    PREF_A(0, 0);
    PREF_A(1, 32);
    for (int ks = 0; ks < 5; ++ks) {
        CP_WAIT1();
        __syncthreads();
        PREF_A((ks + 2) % 3, (ks + 2) * 32);
        uint32_t base = sb + (ks % 3) * 32768;
        #pragma unroll
        for (int c = 0; c < 2; ++c) {
            uint32_t ah[2][4], al[2][4];
            #pragma unroll
            for (int mt = 0; mt < 2; ++mt) {
                ldsm4(ah[mt], a64(base,        wm * 32 + mt * 16, ln, c));
                ldsm4(al[mt], a64(base + 8192, wm * 32 + mt * 16, ln, c));
            }
            #pragma unroll
            for (int p = 0; p < 4; ++p) {
                uint32_t bh[4], bl[4];
                ldsm4(bh, a64(base + 16384, wn * 64 + p * 16, ln, c));
                ldsm4(bl, a64(base + 24576, wn * 64 + p * 16, ln, c));
                MMA_BLK(acc[0][2*p], acc[0][2*p+1], acc[1][2*p], acc[1][2*p+1], ah, al, bh, bl);
            }
        }
    }
    #undef PREF_A

    __nv_bfloat16* WH = &g_wbh[0][0][0][0];
    __nv_bfloat16* WL = &g_wbl[0][0][0][0];
    int yb = 2 * (ln & 3);
    #pragma unroll
    for (int mt = 0; mt < 2; ++mt) {
        int mA = m0 + wm * 32 + mt * 16 + (ln >> 2);
        #pragma unroll
        for (int nt = 0; nt < 8; ++nt) {
            int n = n0 + wn * 64 + nt * 8 + yb;
            size_t off0 = ((size_t)(q * BZ + mA)) * 25600 + n;
            size_t off1 = off0 + (size_t)8 * 25600;
            uint32_t h, l;
            split_pack(acc[mt][nt][0], acc[mt][nt][1], h, l);
            *(uint32_t*)(WH + off0) = h; *(uint32_t*)(WL + off0) = l;
            split_pack(acc[mt][nt][2], acc[mt][nt][3], h, l);
            *(uint32_t*)(WH + off1) = h; *(uint32_t*)(WL + off1) = l;
        }
    }
}

// ---------------- fused B+C per (q,bz): 256 thr, 2 CTA/SM (R14 exact) -------
__device__ __forceinline__ void prefB(uint32_t sb, int slot, int k0, int tid,
    const __nv_bfloat16* Xh, const __nv_bfloat16* Xl,
    const __nv_bfloat16* Wh, const __nv_bfloat16* Wl)
{
    if (k0 < Dp) {
        for (int t = tid; t < 1152; t += 256) {
            uint32_t dst; const __nv_bfloat16* g;
            if (t < 512) {
                int img = t >> 8, rr = (t >> 1) & 127, u = t & 1;
                dst = sb + slot * 18432 + img * 4096 + swz(rr, u);
                g = (img ? Xl : Xh) + (size_t)rr * Dp + k0 + u * 8;
            } else {
                int t2 = t - 512;
                int img = t2 / 320, r2 = t2 - img * 320;
                int rr = r2 >> 1, u = r2 & 1;
                dst = sb + slot * 18432 + 8192 + img * 5120 + swz(rr, u);
                g = (img ? Wl : Wh) + (size_t)rr * Dp + k0 + u * 8;
            }
            cpa16(dst, g);
        }
    }
    CP_COMMIT();
}

__global__ void __launch_bounds__(256, 2) k_fusedBC(float* __restrict__ out)
{
    extern __shared__ __align__(16) unsigned char dynsm[];
    uint32_t sb = smem_u32(dynsm);
    int q = blockIdx.y, bz = blockIdx.x, b = bz >> 7, z = bz & 127;
    int tid = threadIdx.x, w = tid >> 5, ln = tid & 31;
    int wm = w & 3, wn = w >> 2;                    // stage B mapping (4x2)
    int tm = (w < 4) ? w : 7 - w, tn = w >> 2;      // stage C mapping (balanced)
    int pb0 = (q == 0) ? 0 : max(0, min(4, 2 * tm - 4 * tn));

    const __nv_bfloat16 *Xh = &g_eh[c_XI[q]][b*128][0], *Xl = &g_el[c_XI[q]][b*128][0];
    const __nv_bfloat16 *Wh = &g_wbh[q][bz][0][0],      *Wl = &g_wbl[q][bz][0][0];
    const __nv_bfloat16 *Yh = &g_eh[c_YI[q]][b*128][0], *Yl = &g_el[c_YI[q]][b*128][0];

    // ---- stage B (warp tile 32x80, k16, 3-slot, 1 sync/iter)
    float accB[2][10][4];
    #pragma unroll
    for (int mt = 0; mt < 2; ++mt)
        #pragma unroll
        for (int i = 0; i < 10; ++i)
            #pragma unroll
            for (int c = 0; c < 4; ++c) accB[mt][i][c] = 0.f;

    prefB(sb, 0, 0,  tid, Xh, Xl, Wh, Wl);
    prefB(sb, 1, 16, tid, Xh, Xl, Wh, Wl);
    for (int ks = 0; ks < 10; ++ks) {
        CP_WAIT1();
        __syncthreads();
        prefB(sb, (ks + 2) % 3, (ks + 2) * 16, tid, Xh, Xl, Wh, Wl);
        uint32_t base = sb + (ks % 3) * 18432;
        uint32_t ah[2][4], al[2][4];
        #pragma unroll
        for (int mt = 0; mt < 2; ++mt) {
            ldsm4(ah[mt], lds_addr(base,        wm * 32 + mt * 16, ln));
            ldsm4(al[mt], lds_addr(base + 4096, wm * 32 + mt * 16, ln));
        }
        #pragma unroll
        for (int p = 0; p < 5; ++p) {
            uint32_t bh[4], bl[4];
            ldsm4(bh, lds_addr(base + 8192,  wn * 80 + p * 16, ln));
            ldsm4(bl, lds_addr(base + 13312, wn * 80 + p * 16, ln));
            MMA_BLK(accB[0][2*p], accB[0][2*p+1], accB[1][2*p], accB[1][2*p+1], ah, al, bh, bl);
        }
    }
    CP_WAIT0();
    __syncthreads();   // stage-B smem reads done; region reused for v images

    // ---- Y chunk prefetch macro (k16 chunks, 3 slots at [81920,106496))
    #define PREF_Y(slot, kc) do { \
        if ((kc) < Dp) { \
            int t = tid; \
            _Pragma("unroll") \
            for (int it = 0; it < 2; ++it, t += 256) { \
                int img = t >> 8, r2 = t & 255; \
                int row = r2 >> 1, u = r2 & 1; \
                cpa16(sb + 81920 + (slot) * 8192 + img * 4096 + swz(row, u), \
                      (img ? Yl : Yh) + (size_t)row * Dp + (kc) + u * 8); \
            } \
        } \
        CP_COMMIT(); \
    } while(0)

    PREF_Y(0, 0);
    PREF_Y(1, 16);

    // ---- v -> split-bf16 smem images at [0,81920)  (hi@0, lo@40960)
    #pragma unroll
    for (int mt = 0; mt < 2; ++mt) {
        #pragma unroll
        for (int n8 = 0; n8 < 10; ++n8) {
            int j  = wn * 80 + n8 * 8 + 2 * (ln & 3);
            int x1 = wm * 32 + mt * 16 + (ln >> 2);
            uint32_t h, l;
            split_pack(accB[mt][n8][0], accB[mt][n8][1], h, l);
            *(uint32_t*)(dynsm + voff(x1, j))         = h;
            *(uint32_t*)(dynsm + 40960 + voff(x1, j)) = l;
            split_pack(accB[mt][n8][2], accB[mt][n8][3], h, l);
            *(uint32_t*)(dynsm + voff(x1 + 8, j))         = h;
            *(uint32_t*)(dynsm + 40960 + voff(x1 + 8, j)) = l;
        }
    }

    // ---- stage C (warp tile 32x64, A from v-images, B from streamed Y)
    float accC[2][8][4];
    #pragma unroll
    for (int mt = 0; mt < 2; ++mt)
        #pragma unroll
        for (int i = 0; i < 8; ++i)
            #pragma unroll
            for (int c = 0; c < 4; ++c) accC[mt][i][c] = 0.f;

    for (int kk = 0; kk < 10; ++kk) {
        CP_WAIT1();
        __syncthreads();          // (first iter also publishes v images)
        PREF_Y((kk + 2) % 3, (kk + 2) * 16);
        uint32_t ybase = sb + 81920 + (kk % 3) * 8192;
        int u0 = kk * 2;
        uint32_t ah[2][4], al[2][4];
        #pragma unroll
        for (int mt = 0; mt < 2; ++mt) {
            ldsm4(ah[mt], ldsV(sb,         tm * 32 + mt * 16, ln, u0));
            ldsm4(al[mt], ldsV(sb + 40960, tm * 32 + mt * 16, ln, u0));
        }
        #pragma unroll
        for (int pb = 0; pb < 4; ++pb) {
            if (pb >= pb0) {
                uint32_t bh[4], bl[4];
                ldsm4(bh, lds_addr(ybase,        tn * 64 + pb * 16, ln));
                ldsm4(bl, lds_addr(ybase + 4096, tn * 64 + pb * 16, ln));
                MMA_BLK(accC[0][2*pb], accC[0][2*pb+1], accC[1][2*pb], accC[1][2*pb+1],
                        ah, al, bh, bl);
            }
        }
    }
    #undef PREF_Y
    CP_WAIT0();
    __syncthreads();   // stage-C smem reads done; reuse region for s-tile

    // ---- epilogue: stage s tile, triu_sym on read, coalesced out
    float* ss = (float*)dynsm;   // [128][130]
    #pragma unroll
    for (int mt = 0; mt < 2; ++mt) {
        int x = tm * 32 + mt * 16 + (ln >> 2);
        #pragma unroll
        for (int nt = 0; nt < 8; ++nt) {
            int y = tn * 64 + nt * 8 + 2 * (ln & 3);
            ss[x * 130 + y]           = accC[mt][nt][0];
            ss[x * 130 + y + 1]       = accC[mt][nt][1];
            ss[(x + 8) * 130 + y]     = accC[mt][nt][2];
            ss[(x + 8) * 130 + y + 1] = accC[mt][nt][3];
        }
    }
    __syncthreads();

    bool dosym = (q != 0);
    float* o;
    if (q < 4) o = out + (size_t)q * 4194304 + (size_t)bz * 16384;
    else       o = &g_cp[(q - 4) * 2 + b][z][0][0];
    int c0 = ln * 4;
    #pragma unroll
    for (int rr = 0; rr < 16; ++rr) {
        int r = w * 16 + rr;
        const float* pr2 = ss + r * 130;
        float4 v;
        v.x = (!dosym || r <= c0    ) ? pr2[c0]     : ss[(c0)     * 130 + r];
        v.y = (!dosym || r <= c0 + 1) ? pr2[c0 + 1] : ss[(c0 + 1) * 130 + r];
        v.z = (!dosym || r <= c0 + 2) ? pr2[c0 + 2] : ss[(c0 + 2) * 130 + r];
        v.w = (!dosym || r <= c0 + 3) ? pr2[c0 + 3] : ss[(c0 + 3) * 130 + r];
        *(float4*)(o + (size_t)r * 128 + c0) = v;
    }
}

// ---------------- co-parent permute: g_cp[t*2+b][z][x][y] -> out[b][x][y][z]
__global__ void k_cop(float* __restrict__ out)
{
    __shared__ float ts[32][33];
    int tile = blockIdx.x;
    int x    = blockIdx.y;
    int tb   = blockIdx.z;
    int z0 = (tile >> 2) * 32, y0 = (tile & 3) * 32;
    int tx = threadIdx.x, ty = threadIdx.y;
    const float* src = &g_cp[tb][0][x][0];
    #pragma unroll
    for (int i = ty; i < 32; i += 8)
        ts[i][tx] = src[(size_t)(z0 + i) * 16384 + y0 + tx];
    __syncthreads();
    float* dst = out + (size_t)(4 + (tb >> 1)) * 4194304 + (size_t)(tb & 1) * 2097152
               + (size_t)x * 16384;
    #pragma unroll
    for (int i = ty; i < 32; i += 8)
        dst[(size_t)(y0 + i) * 128 + z0 + tx] = ts[tx][i];
}

// ---------------------------------------------------------------------------
extern "C" void kernel_launch(void* const* d_in, const int* in_sizes, int n_in,
                              void* d_out, int out_size)
{
    const float* x      = (const float*)d_in[0];
    const float* W_sh   = (const float*)d_in[1];
    const float* b_sh   = (const float*)d_in[2];
    const float* W_st   = (const float*)d_in[3];
    const float* b_st   = (const float*)d_in[4];
    const float* W_p    = (const float*)d_in[5];
    const float* b_p    = (const float*)d_in[6];
    const float* T_pt   = (const float*)d_in[7];
    const float* T_ph   = (const float*)d_in[8];
    const float* T_phsib= (const float*)d_in[9];
    const float* T_ptsib= (const float*)d_in[10];
    const float* T_phcop= (const float*)d_in[11];
    const float* T_ptcop= (const float*)d_in[12];

    static bool attr_done = false;
    if (!attr_done) {
        cudaFuncSetAttribute(k_stageA,  cudaFuncAttributeMaxDynamicSharedMemorySize, 98304);
        cudaFuncSetAttribute(k_fusedBC, cudaFuncAttributeMaxDynamicSharedMemorySize, 106496);
        attr_done = true;
    }

    k_mlp_part<<<dim3(3, 8, 16), 160>>>(x, W_sh, W_st, W_p);
    k_fin     <<<240, 256>>>(b_sh, b_st, b_p);
    // q order: 0=T_ph 1=T_pt 2=T_phsib 3=T_ptsib 4=T_phcop 5=T_ptcop
    k_timg    <<<dim3(5, D, 6), 256>>>(T_ph, T_pt, T_phsib, T_ptsib, T_phcop, T_ptcop);
    k_stageA  <<<dim3(188, 2, 6), 256, 98304>>>();
    k_fusedBC <<<dim3(BZ, 6), 256, 106496>>>((float*)d_out);
    k_cop     <<<dim3(16, 128, 4), dim3(32, 8)>>>((float*)d_out);
}

// round 16
// speedup vs baseline: 1.4282x; 1.0234x over previous
#include <cuda_runtime.h>
#include <cuda_bf16.h>
#include <cstdint>

#define D      150
#define Dp     160
#define NTOT   25600     // Dp*Dp, n = j*160 + i
#define BZ     256
#define DIN    1024

// ---------------- scratch (__device__ globals; zero-init; pads never written)
__device__ __align__(16) float g_part[3][8][BZ][Dp];         // mlp split-K partials
__device__ __align__(16) __nv_bfloat16 g_eh[3][BZ][Dp];      // emb hi image
__device__ __align__(16) __nv_bfloat16 g_el[3][BZ][Dp];      // emb lo image
__device__ __align__(16) __nv_bfloat16 g_tbh[6][NTOT][Dp];   // T image [q][n][k] hi
__device__ __align__(16) __nv_bfloat16 g_tbl[6][NTOT][Dp];   // lo
__device__ __align__(16) __nv_bfloat16 g_wbh[6][BZ][Dp][Dp]; // w image [q][bz][j][i] hi
__device__ __align__(16) __nv_bfloat16 g_wbl[6][BZ][Dp][Dp]; // lo
__device__ __align__(16) float g_cp[4][128][128][128];       // co-parent staging

// q0 span_psh (no sym)  q1 span_pst (sym)  q2 ph_sib  q3 pt_sib
// q4 ph_cop  q5 pt_cop  (q4,q5 permuted out via g_cp + k_cop)
__constant__ int c_ZI[6] = {2,2,2,2,0,1};
__constant__ int c_XI[6] = {0,0,0,1,2,2};
__constant__ int c_YI[6] = {1,1,0,1,2,2};

// ---------------- low-level helpers ----------------------------------------
__device__ __forceinline__ uint32_t smem_u32(const void* p){
    uint32_t a;
    asm("{ .reg .u64 t; cvta.to.shared.u64 t, %1; cvt.u32.u64 %0, t; }" : "=r"(a) : "l"(p));
    return a;
}
__device__ __forceinline__ void split_pack(float a, float b, uint32_t& h, uint32_t& l){
    __nv_bfloat16 ah = __float2bfloat16(a), bh = __float2bfloat16(b);
    __nv_bfloat16 al = __float2bfloat16(a - __bfloat162float(ah));
    __nv_bfloat16 bl = __float2bfloat16(b - __bfloat162float(bh));
    h = (uint32_t)__bfloat16_as_ushort(ah) | ((uint32_t)__bfloat16_as_ushort(bh) << 16);
    l = (uint32_t)__bfloat16_as_ushort(al) | ((uint32_t)__bfloat16_as_ushort(bl) << 16);
}
__device__ __forceinline__ void mma16816(float* c, const uint32_t* a, uint32_t b0, uint32_t b1){
    asm volatile("mma.sync.aligned.m16n8k16.row.col.f32.bf16.bf16.f32 "
        "{%0,%1,%2,%3}, {%4,%5,%6,%7}, {%8,%9}, {%0,%1,%2,%3};"
        : "+f"(c[0]), "+f"(c[1]), "+f"(c[2]), "+f"(c[3])
        : "r"(a[0]), "r"(a[1]), "r"(a[2]), "r"(a[3]), "r"(b0), "r"(b1));
}
__device__ __forceinline__ void ldsm4(uint32_t* r, uint32_t a){
    asm volatile("ldmatrix.sync.aligned.m8n8.x4.shared.b16 {%0,%1,%2,%3}, [%4];"
        : "=r"(r[0]), "=r"(r[1]), "=r"(r[2]), "=r"(r[3]) : "r"(a));
}
__device__ __forceinline__ void cpa16(uint32_t s, const void* g){
    asm volatile("cp.async.cg.shared.global [%0], [%1], 16;" :: "r"(s), "l"(g));
}
#define CP_COMMIT() asm volatile("cp.async.commit_group;" ::: "memory")
#define CP_WAIT1()  asm volatile("cp.async.wait_group 1;" ::: "memory")
#define CP_WAIT0()  asm volatile("cp.async.wait_group 0;" ::: "memory")

// 32B-row layout (k16 chunks): 2x16B units/row, XOR swizzle (R7-proven)
__device__ __forceinline__ uint32_t swz(int row, int u){
    return (uint32_t)(row * 32 + (((u ^ (row >> 2)) & 1) << 4));
}
__device__ __forceinline__ uint32_t lds_addr(uint32_t base, int r0, int ln){
    int g = ln >> 3;
    int row = r0 + ((g & 1) << 3) + (ln & 7);
    return base + swz(row, g >> 1);
}
// 64B-row layout (k32 chunks), R9-proven
__device__ __forceinline__ uint32_t swz64(int row, int u){
    return (uint32_t)(row * 64 + 16 * ((u ^ (row >> 1)) & 3));
}
__device__ __forceinline__ uint32_t a64(uint32_t base, int r0, int ln, int c){
    int g = ln >> 3;
    int row = r0 + ((g & 1) << 3) + (ln & 7);
    return base + swz64(row, 2 * c + (g >> 1));
}
// 320B-row image layout (v), R7-proven
__device__ __forceinline__ uint32_t voff(int row, int j){
    return (uint32_t)(row * 320 + 16 * ((j >> 3) ^ ((row >> 1) & 3)) + (j & 7) * 2);
}
__device__ __forceinline__ uint32_t vuoff(int row, int u){
    return (uint32_t)(row * 320 + 16 * (u ^ ((row >> 1) & 3)));
}
__device__ __forceinline__ uint32_t ldsV(uint32_t base, int r0, int ln, int u0){
    int g = ln >> 3;
    int row = r0 + ((g & 1) << 3) + (ln & 7);
    return base + vuoff(row, u0 + (g >> 1));
}
// ILP-4 split-major 12-MMA block
#define MMA_BLK(t00, t01, t10, t11, ah, al, bh, bl) do { \
    mma16816(t00, ah[0], bh[0], bh[2]); \
    mma16816(t01, ah[0], bh[1], bh[3]); \
    mma16816(t10, ah[1], bh[0], bh[2]); \
    mma16816(t11, ah[1], bh[1], bh[3]); \
    mma16816(t00, ah[0], bl[0], bl[2]); \
    mma16816(t01, ah[0], bl[1], bl[3]); \
    mma16816(t10, ah[1], bl[0], bl[2]); \
    mma16816(t11, ah[1], bl[1], bl[3]); \
    mma16816(t00, al[0], bh[0], bh[2]); \
    mma16816(t01, al[0], bh[1], bh[3]); \
    mma16816(t10, al[1], bh[0], bh[2]); \
    mma16816(t11, al[1], bh[1], bh[3]); \
} while(0)

// ---------------- MLP split-K partials (R15 exact) ---------------------------
__global__ void k_mlp_part(const float* __restrict__ x,
                           const float* __restrict__ W0,
                           const float* __restrict__ W1,
                           const float* __restrict__ W2)
{
    int e = blockIdx.x, ks = blockIdx.y, r0 = blockIdx.z * 16;
    const float* W = (e == 0) ? W0 : (e == 1) ? W1 : W2;
    __shared__ float xs[16][128];
    int tid = threadIdx.x;
    for (int i = tid; i < 16 * 128; i += 160) {
        int r = i >> 7, k = i & 127;
        xs[r][k] = x[(size_t)(r0 + r) * DIN + ks * 128 + k];
    }
    __syncthreads();
    if (tid < D) {
        float acc[16];
        #pragma unroll
        for (int r = 0; r < 16; ++r) acc[r] = 0.f;
        #pragma unroll 4
        for (int k = 0; k < 128; ++k) {
            float wv = W[(size_t)(ks * 128 + k) * D + tid];
            #pragma unroll
            for (int r = 0; r < 16; ++r) acc[r] += xs[r][k] * wv;
        }
        #pragma unroll
        for (int r = 0; r < 16; ++r)
            g_part[e][ks][r0 + r][tid] = acc[r];
    }
}

// ---------------- finalize (R15 exact) ---------------------------------------
__global__ void k_fin(const float* __restrict__ b0,
                      const float* __restrict__ b1,
                      const float* __restrict__ b2)
{
    int idx = blockIdx.x * 256 + threadIdx.x;
    if (idx >= 3 * 256 * 80) return;
    int e = idx / 20480, rem = idx % 20480;
    int row = rem / 80, kp = rem % 80;
    const float* bb = (e == 0) ? b0 : (e == 1) ? b1 : b2;
    int c0 = 2 * kp, c1 = 2 * kp + 1;
    float v0 = 0.f, v1 = 0.f;
    if (c0 < D) {
        v0 = bb[c0];
        #pragma unroll
        for (int ks = 0; ks < 8; ++ks) v0 += g_part[e][ks][row][c0];
        v0 = (v0 >= 0.f) ? v0 : 0.1f * v0;
    }
    if (c1 < D) {
        v1 = bb[c1];
        #pragma unroll
        for (int ks = 0; ks < 8; ++ks) v1 += g_part[e][ks][row][c1];
        v1 = (v1 >= 0.f) ? v1 : 0.1f * v1;
    }
    uint32_t h, l;
    split_pack(v0, v1, h, l);
    *(uint32_t*)&g_eh[e][row][c0] = h;
    *(uint32_t*)&g_el[e][row][c0] = l;
}

// ---------------- T[i][k][j] -> TB[q][(j*160+i)][k] hi/lo (per-q) -----------
__global__ void k_timg(const float* __restrict__ T, int q)
{
    int i = blockIdx.y, j0 = blockIdx.x * 32;
    __shared__ float ts[32][152];
    int tid = threadIdx.x;
    for (int t = tid; t < 150 * 32; t += 256) {
        int k = t >> 5, j = t & 31;
        if (j0 + j < D) ts[j][k] = T[(i * D + k) * D + j0 + j];
    }
    __syncthreads();
    for (int t = tid; t < 32 * 75; t += 256) {
        int j = t / 75, kp = t % 75;
        if (j0 + j < D) {
            uint32_t h, l;
            split_pack(ts[j][2*kp], ts[j][2*kp+1], h, l);
            int n = (j0 + j) * Dp + i;
            *(uint32_t*)&g_tbh[q][n][2*kp] = h;
            *(uint32_t*)&g_tbl[q][n][2*kp] = l;
        }
    }
}

// ---------------- stage A (per-q; R14 math exact; 188 N-tiles) ---------------
__global__ void __launch_bounds__(256, 2) k_stageA(int q)
{
    extern __shared__ __align__(16) unsigned char smA[];   // 3 x 32768
    uint32_t sb = smem_u32(smA);
    int m0 = blockIdx.y * 128, n0 = blockIdx.x * 128;
    int tid = threadIdx.x, w = tid >> 5, ln = tid & 31;
    int wm = w & 3, wn = w >> 2;
    int zi = c_ZI[q];

    int pr = tid >> 2, pu = tid & 3;
    uint32_t sw0 = swz64(pr, pu);
    const __nv_bfloat16* gpA[4];
    gpA[0] = &g_eh[zi][0][0]  + (size_t)(m0 + pr) * Dp + pu * 8;
    gpA[1] = &g_el[zi][0][0]  + (size_t)(m0 + pr) * Dp + pu * 8;
    gpA[2] = &g_tbh[q][0][0]  + (size_t)(n0 + pr) * Dp + pu * 8;
    gpA[3] = &g_tbl[q][0][0]  + (size_t)(n0 + pr) * Dp + pu * 8;

    float acc[2][8][4];
    #pragma unroll
    for (int a = 0; a < 2; ++a)
        #pragma unroll
        for (int b = 0; b < 8; ++b)
            #pragma unroll
            for (int c = 0; c < 4; ++c) acc[a][b][c] = 0.f;

    #define PREF_A(slot, kc) do { \
        if ((kc) < Dp) { \
            uint32_t db = sb + (slot) * 32768 + sw0; \
            _Pragma("unroll") \
            for (int a = 0; a < 4; ++a) { \
                cpa16(db + a * 8192,        gpA[a] + (kc)); \
                cpa16(db + a * 8192 + 4096, gpA[a] + 64 * Dp + (kc)); \
            } \
        } \
        CP_COMMIT(); \
    } while(0)

    PREF_A(0, 0);
    PREF_A(1, 32);
    for (int ks = 0; ks < 5; ++ks) {
        CP_WAIT1();
        __syncthreads();
        PREF_A((ks + 2) % 3, (ks + 2) * 32);
        uint32_t base = sb + (ks % 3) * 32768;
        #pragma unroll
        for (int c = 0; c < 2; ++c) {
            uint32_t ah[2][4], al[2][4];
            #pragma unroll
            for (int mt = 0; mt < 2; ++mt) {
                ldsm4(ah[mt], a64(base,        wm * 32 + mt * 16, ln, c));
                ldsm4(al[mt], a64(base + 8192, wm * 32 + mt * 16, ln, c));
            }
            #pragma unroll
            for (int p = 0; p < 4; ++p) {
                uint32_t bh[4], bl[4];
                ldsm4(bh, a64(base + 16384, wn * 64 + p * 16, ln, c));
                ldsm4(bl, a64(base + 24576, wn * 64 + p * 16, ln, c));
                MMA_BLK(acc[0][2*p], acc[0][2*p+1], acc[1][2*p], acc[1][2*p+1], ah, al, bh, bl);
            }
        }
    }
    #undef PREF_A

    __nv_bfloat16* WH = &g_wbh[0][0][0][0];
    __nv_bfloat16* WL = &g_wbl[0][0][0][0];
    int yb = 2 * (ln & 3);
    #pragma unroll
    for (int mt = 0; mt < 2; ++mt) {
        int mA = m0 + wm * 32 + mt * 16 + (ln >> 2);
        #pragma unroll
        for (int nt = 0; nt < 8; ++nt) {
            int n = n0 + wn * 64 + nt * 8 + yb;
            size_t off0 = ((size_t)(q * BZ + mA)) * 25600 + n;
            size_t off1 = off0 + (size_t)8 * 25600;
            uint32_t h, l;
            split_pack(acc[mt][nt][0], acc[mt][nt][1], h, l);
            *(uint32_t*)(WH + off0) = h; *(uint32_t*)(WL + off0) = l;
            split_pack(acc[mt][nt][2], acc[mt][nt][3], h, l);
            *(uint32_t*)(WH + off1) = h; *(uint32_t*)(WL + off1) = l;
        }
    }
}

// ---------------- fused B+C per bz (per-q; R14 math exact) -------------------
__device__ __forceinline__ void prefB(uint32_t sb, int slot, int k0, int tid,
    const __nv_bfloat16* Xh, const __nv_bfloat16* Xl,
    const __nv_bfloat16* Wh, const __nv_bfloat16* Wl)
{
    if (k0 < Dp) {
        for (int t = tid; t < 1152; t += 256) {
            uint32_t dst; const __nv_bfloat16* g;
            if (t < 512) {
                int img = t >> 8, rr = (t >> 1) & 127, u = t & 1;
                dst = sb + slot * 18432 + img * 4096 + swz(rr, u);
                g = (img ? Xl : Xh) + (size_t)rr * Dp + k0 + u * 8;
            } else {
                int t2 = t - 512;
                int img = t2 / 320, r2 = t2 - img * 320;
                int rr = r2 >> 1, u = r2 & 1;
                dst = sb + slot * 18432 + 8192 + img * 5120 + swz(rr, u);
                g = (img ? Wl : Wh) + (size_t)rr * Dp + k0 + u * 8;
            }
            cpa16(dst, g);
        }
    }
    CP_COMMIT();
}

__global__ void __launch_bounds__(256, 2) k_fusedBC(float* __restrict__ out, int q)
{
    extern __shared__ __align__(16) unsigned char dynsm[];
    uint32_t sb = smem_u32(dynsm);
    int bz = blockIdx.x, b = bz >> 7, z = bz & 127;
    int tid = threadIdx.x, w = tid >> 5, ln = tid & 31;
    int wm = w & 3, wn = w >> 2;                    // stage B mapping (4x2)
    int tm = (w < 4) ? w : 7 - w, tn = w >> 2;      // stage C mapping (balanced)
    int pb0 = (q == 0) ? 0 : max(0, min(4, 2 * tm - 4 * tn));

    const __nv_bfloat16 *Xh = &g_eh[c_XI[q]][b*128][0], *Xl = &g_el[c_XI[q]][b*128][0];
    const __nv_bfloat16 *Wh = &g_wbh[q][bz][0][0],      *Wl = &g_wbl[q][bz][0][0];
    const __nv_bfloat16 *Yh = &g_eh[c_YI[q]][b*128][0], *Yl = &g_el[c_YI[q]][b*128][0];

    // ---- stage B (warp tile 32x80, k16, 3-slot, 1 sync/iter)
    float accB[2][10][4];
    #pragma unroll
    for (int mt = 0; mt < 2; ++mt)
        #pragma unroll
        for (int i = 0; i < 10; ++i)
            #pragma unroll
            for (int c = 0; c < 4; ++c) accB[mt][i][c] = 0.f;

    prefB(sb, 0, 0,  tid, Xh, Xl, Wh, Wl);
    prefB(sb, 1, 16, tid, Xh, Xl, Wh, Wl);
    for (int ks = 0; ks < 10; ++ks) {
        CP_WAIT1();
        __syncthreads();
        prefB(sb, (ks + 2) % 3, (ks + 2) * 16, tid, Xh, Xl, Wh, Wl);
        uint32_t base = sb + (ks % 3) * 18432;
        uint32_t ah[2][4], al[2][4];
        #pragma unroll
        for (int mt = 0; mt < 2; ++mt) {
            ldsm4(ah[mt], lds_addr(base,        wm * 32 + mt * 16, ln));
            ldsm4(al[mt], lds_addr(base + 4096, wm * 32 + mt * 16, ln));
        }
        #pragma unroll
        for (int p = 0; p < 5; ++p) {
            uint32_t bh[4], bl[4];
            ldsm4(bh, lds_addr(base + 8192,  wn * 80 + p * 16, ln));
            ldsm4(bl, lds_addr(base + 13312, wn * 80 + p * 16, ln));
            MMA_BLK(accB[0][2*p], accB[0][2*p+1], accB[1][2*p], accB[1][2*p+1], ah, al, bh, bl);
        }
    }
    CP_WAIT0();
    __syncthreads();   // stage-B smem reads done; region reused for v images

    // ---- Y chunk prefetch macro (k16 chunks, 3 slots at [81920,106496))
    #define PREF_Y(slot, kc) do { \
        if ((kc) < Dp) { \
            int t = tid; \
            _Pragma("unroll") \
            for (int it = 0; it < 2; ++it, t += 256) { \
                int img = t >> 8, r2 = t & 255; \
                int row = r2 >> 1, u = r2 & 1; \
                cpa16(sb + 81920 + (slot) * 8192 + img * 4096 + swz(row, u), \
                      (img ? Yl : Yh) + (size_t)row * Dp + (kc) + u * 8); \
            } \
        } \
        CP_COMMIT(); \
    } while(0)

    PREF_Y(0, 0);
    PREF_Y(1, 16);

    // ---- v -> split-bf16 smem images at [0,81920)  (hi@0, lo@40960)
    #pragma unroll
    for (int mt = 0; mt < 2; ++mt) {
        #pragma unroll
        for (int n8 = 0; n8 < 10; ++n8) {
            int j  = wn * 80 + n8 * 8 + 2 * (ln & 3);
            int x1 = wm * 32 + mt * 16 + (ln >> 2);
            uint32_t h, l;
            split_pack(accB[mt][n8][0], accB[mt][n8][1], h, l);
            *(uint32_t*)(dynsm + voff(x1, j))         = h;
            *(uint32_t*)(dynsm + 40960 + voff(x1, j)) = l;
            split_pack(accB[mt][n8][2], accB[mt][n8][3], h, l);
            *(uint32_t*)(dynsm + voff(x1 + 8, j))         = h;
            *(uint32_t*)(dynsm + 40960 + voff(x1 + 8, j)) = l;
        }
    }

    // ---- stage C (warp tile 32x64, A from v-images, B from streamed Y)
    float accC[2][8][4];
    #pragma unroll
    for (int mt = 0; mt < 2; ++mt)
        #pragma unroll
        for (int i = 0; i < 8; ++i)
            #pragma unroll
            for (int c = 0; c < 4; ++c) accC[mt][i][c] = 0.f;

    for (int kk = 0; kk < 10; ++kk) {
        CP_WAIT1();
        __syncthreads();          // (first iter also publishes v images)
        PREF_Y((kk + 2) % 3, (kk + 2) * 16);
        uint32_t ybase = sb + 81920 + (kk % 3) * 8192;
        int u0 = kk * 2;
        uint32_t ah[2][4], al[2][4];
        #pragma unroll
        for (int mt = 0; mt < 2; ++mt) {
            ldsm4(ah[mt], ldsV(sb,         tm * 32 + mt * 16, ln, u0));
            ldsm4(al[mt], ldsV(sb + 40960, tm * 32 + mt * 16, ln, u0));
        }
        #pragma unroll
        for (int pb = 0; pb < 4; ++pb) {
            if (pb >= pb0) {
                uint32_t bh[4], bl[4];
                ldsm4(bh, lds_addr(ybase,        tn * 64 + pb * 16, ln));
                ldsm4(bl, lds_addr(ybase + 4096, tn * 64 + pb * 16, ln));
                MMA_BLK(accC[0][2*pb], accC[0][2*pb+1], accC[1][2*pb], accC[1][2*pb+1],
                        ah, al, bh, bl);
            }
        }
    }
    #undef PREF_Y
    CP_WAIT0();
    __syncthreads();   // stage-C smem reads done; reuse region for s-tile

    // ---- epilogue: stage s tile, triu_sym on read, coalesced out
    float* ss = (float*)dynsm;   // [128][130]
    #pragma unroll
    for (int mt = 0; mt < 2; ++mt) {
        int x = tm * 32 + mt * 16 + (ln >> 2);
        #pragma unroll
        for (int nt = 0; nt < 8; ++nt) {
            int y = tn * 64 + nt * 8 + 2 * (ln & 3);
            ss[x * 130 + y]           = accC[mt][nt][0];
            ss[x * 130 + y + 1]       = accC[mt][nt][1];
            ss[(x + 8) * 130 + y]     = accC[mt][nt][2];
            ss[(x + 8) * 130 + y + 1] = accC[mt][nt][3];
        }
    }
    __syncthreads();

    bool dosym = (q != 0);
    float* o;
    if (q < 4) o = out + (size_t)q * 4194304 + (size_t)bz * 16384;
    else       o = &g_cp[(q - 4) * 2 + b][z][0][0];
    int c0 = ln * 4;
    #pragma unroll
    for (int rr = 0; rr < 16; ++rr) {
        int r = w * 16 + rr;
        const float* pr2 = ss + r * 130;
        float4 v;
        v.x = (!dosym || r <= c0    ) ? pr2[c0]     : ss[(c0)     * 130 + r];
        v.y = (!dosym || r <= c0 + 1) ? pr2[c0 + 1] : ss[(c0 + 1) * 130 + r];
        v.z = (!dosym || r <= c0 + 2) ? pr2[c0 + 2] : ss[(c0 + 2) * 130 + r];
        v.w = (!dosym || r <= c0 + 3) ? pr2[c0 + 3] : ss[(c0 + 3) * 130 + r];
        *(float4*)(o + (size_t)r * 128 + c0) = v;
    }
}

// ---------------- co-parent permute: g_cp[t*2+b][z][x][y] -> out[b][x][y][z]
__global__ void k_cop(float* __restrict__ out)
{
    __shared__ float ts[32][33];
    int tile = blockIdx.x;
    int x    = blockIdx.y;
    int tb   = blockIdx.z;
    int z0 = (tile >> 2) * 32, y0 = (tile & 3) * 32;
    int tx = threadIdx.x, ty = threadIdx.y;
    const float* src = &g_cp[tb][0][x][0];
    #pragma unroll
    for (int i = ty; i < 32; i += 8)
        ts[i][tx] = src[(size_t)(z0 + i) * 16384 + y0 + tx];
    __syncthreads();
    float* dst = out + (size_t)(4 + (tb >> 1)) * 4194304 + (size_t)(tb & 1) * 2097152
               + (size_t)x * 16384;
    #pragma unroll
    for (int i = ty; i < 32; i += 8)
        dst[(size_t)(y0 + i) * 128 + z0 + tx] = ts[tx][i];
}

// ---------------------------------------------------------------------------
extern "C" void kernel_launch(void* const* d_in, const int* in_sizes, int n_in,
                              void* d_out, int out_size)
{
    const float* x      = (const float*)d_in[0];
    const float* W_sh   = (const float*)d_in[1];
    const float* b_sh   = (const float*)d_in[2];
    const float* W_st   = (const float*)d_in[3];
    const float* b_st   = (const float*)d_in[4];
    const float* W_p    = (const float*)d_in[5];
    const float* b_p    = (const float*)d_in[6];
    const float* T_pt   = (const float*)d_in[7];
    const float* T_ph   = (const float*)d_in[8];
    const float* T_phsib= (const float*)d_in[9];
    const float* T_ptsib= (const float*)d_in[10];
    const float* T_phcop= (const float*)d_in[11];
    const float* T_ptcop= (const float*)d_in[12];

    static bool init_done = false;
    static cudaStream_t s1, s2;
    static cudaEvent_t e0, eEnd, tEv[6], aEv[6];
    if (!init_done) {
        cudaFuncSetAttribute(k_stageA,  cudaFuncAttributeMaxDynamicSharedMemorySize, 98304);
        cudaFuncSetAttribute(k_fusedBC, cudaFuncAttributeMaxDynamicSharedMemorySize, 106496);
        cudaStreamCreateWithFlags(&s1, cudaStreamNonBlocking);
        cudaStreamCreateWithFlags(&s2, cudaStreamNonBlocking);
        cudaEventCreateWithFlags(&e0,   cudaEventDisableTiming);
        cudaEventCreateWithFlags(&eEnd, cudaEventDisableTiming);
        for (int q = 0; q < 6; ++q) {
            cudaEventCreateWithFlags(&tEv[q], cudaEventDisableTiming);
            cudaEventCreateWithFlags(&aEv[q], cudaEventDisableTiming);
        }
        init_done = true;
    }

    // q order: 0=T_ph 1=T_pt 2=T_phsib 3=T_ptsib 4=T_phcop 5=T_ptcop
    const float* Ts[6] = {T_ph, T_pt, T_phsib, T_ptsib, T_phcop, T_ptcop};

    // fork: s1 runs T-image builds concurrently with mlp + stageA chain
    cudaEventRecord(e0, 0);
    cudaStreamWaitEvent(s1, e0, 0);
    for (int q = 0; q < 6; ++q) {
        k_timg<<<dim3(5, D), 256, 0, s1>>>(Ts[q], q);
        cudaEventRecord(tEv[q], s1);
    }

    // legacy stream: mlp chain, then per-q stage A gated on timg[q]
    k_mlp_part<<<dim3(3, 8, 16), 160>>>(x, W_sh, W_st, W_p);
    k_fin     <<<240, 256>>>(b_sh, b_st, b_p);
    for (int q = 0; q < 6; ++q) {
        cudaStreamWaitEvent(0, tEv[q], 0);
        k_stageA<<<dim3(188, 2), 256, 98304>>>(q);
        cudaEventRecord(aEv[q], 0);
    }

    // s2: per-q fused B+C gated on stageA[q]; then co-parent permute; join
    for (int q = 0; q < 6; ++q) {
        cudaStreamWaitEvent(s2, aEv[q], 0);
        k_fusedBC<<<BZ, 256, 106496, s2>>>((float*)d_out, q);
    }
    k_cop<<<dim3(16, 128, 4), dim3(32, 8), 0, s2>>>((float*)d_out);
    cudaEventRecord(eEnd, s2);
    cudaStreamWaitEvent(0, eEnd, 0);
}